// round 11
// baseline (speedup 1.0000x reference)
#include <cuda_runtime.h>
#include <cuda_bf16.h>

// ---------------- problem constants ----------------
#define BB 8
#define NN 131072
#define SS 1024
#define KK 64
#define CC 32
#define HH 64          // 2*C
#define D1 38          // C + 6
#define D2 70          // H + 6
#define H3 256         // 4*H

#define CH 16          // neighbor chunk size (per warp-query)
#define NCHUNK (KK/CH) // 4
#define WQ 8           // warp-queries per block

// output layout (flattened concat of the 4 returned tensors)
#define OFF_LOCS  0
#define OFF_OUT   (BB*SS*3)                  // 24576
#define OFF_BOXES (OFF_OUT + BB*HH*SS)       // 548864
#define OFF_INDS  (OFF_BOXES + BB*SS*6)      // 598016

typedef unsigned long long ull;

// ---------------- f32x2 packed helpers (sm_100+) ----------------
__device__ __forceinline__ ull pack2(float lo, float hi) {
    ull r; asm("mov.b64 %0, {%1, %2};" : "=l"(r) : "f"(lo), "f"(hi)); return r;
}
__device__ __forceinline__ void unpack2(ull v, float& lo, float& hi) {
    asm("mov.b64 {%0, %1}, %2;" : "=f"(lo), "=f"(hi) : "l"(v));
}
__device__ __forceinline__ void fma2(ull& d, ull a, ull b) {
    asm("fma.rn.f32x2 %0, %1, %2, %0;" : "+l"(d) : "l"(a), "l"(b));
}

// ---------------- scratch (device globals; no allocation allowed) ----------
__device__ float g_feats_nc[BB * NN * CC];   // [B,N,C] transposed feats
__device__ float g_dimbox  [BB * NN * 3];
__device__ float g_fps_locs[BB * SS * 3];
__device__ float g_fps_dim [BB * SS * 3];
__device__ float g_newfeat [BB * SS * HH];   // stage1 output == identity
__device__ float g_h2max   [BB * SS * HH];   // stage2 output

// ---------------- prep: transpose feats, compute dim boxes ----------------
__global__ __launch_bounds__(256) void prep_kernel(
    const float* __restrict__ feats, const float* __restrict__ boxes)
{
    int idx = blockIdx.x * blockDim.x + threadIdx.x;   // over B*N
    if (idx >= BB * NN) return;
    int b = idx >> 17;
    int n = idx & (NN - 1);

    float tmp[CC];
    #pragma unroll
    for (int c = 0; c < CC; c++)
        tmp[c] = feats[(b * CC + c) * NN + n];

    float4* dst = (float4*)(g_feats_nc + ((size_t)idx << 5));
    #pragma unroll
    for (int q = 0; q < 8; q++)
        dst[q] = make_float4(tmp[4*q], tmp[4*q+1], tmp[4*q+2], tmp[4*q+3]);

    const float* bx = boxes + (size_t)idx * 6;
    float* dd = g_dimbox + (size_t)idx * 3;
    dd[0] = bx[3] - bx[0];
    dd[1] = bx[4] - bx[1];
    dd[2] = bx[5] - bx[2];
}

// ---------------- fps gather ----------
__global__ __launch_bounds__(256) void fps_kernel(
    const float* __restrict__ locs, const float* __restrict__ boxes,
    const int* __restrict__ fps_inds, float* __restrict__ out)
{
    int idx = blockIdx.x * blockDim.x + threadIdx.x;   // over B*S
    if (idx >= BB * SS) return;
    int b = idx >> 10;
    int j = fps_inds[idx];

    const float* lp = locs + ((size_t)b * NN + j) * 3;
    float l0 = lp[0], l1 = lp[1], l2 = lp[2];
    g_fps_locs[idx*3+0] = l0; g_fps_locs[idx*3+1] = l1; g_fps_locs[idx*3+2] = l2;
    out[OFF_LOCS + idx*3 + 0] = l0;
    out[OFF_LOCS + idx*3 + 1] = l1;
    out[OFF_LOCS + idx*3 + 2] = l2;

    const float* bx = boxes + ((size_t)b * NN + j) * 6;
    float b0 = bx[0], b1 = bx[1], b2 = bx[2], b3 = bx[3], b4 = bx[4], b5 = bx[5];
    g_fps_dim[idx*3+0] = b3 - b0;
    g_fps_dim[idx*3+1] = b4 - b1;
    g_fps_dim[idx*3+2] = b5 - b2;
    out[OFF_BOXES + idx*6 + 0] = b0;
    out[OFF_BOXES + idx*6 + 1] = b1;
    out[OFF_BOXES + idx*6 + 2] = b2;
    out[OFF_BOXES + idx*6 + 3] = b3;
    out[OFF_BOXES + idx*6 + 4] = b4;
    out[OFF_BOXES + idx*6 + 5] = b5;

    out[OFF_INDS + idx] = (float)j;
}

// ================= stage 1: 1 warp per query, 4 chunks of 16 =============
// smem floats: wa[1216] wb[2048] ba[32] bb[64] | per-q: g1[38*16] h1[32*16]
#define S1_BASE (D1*CC + CC*HH + CC + HH)         // 3360
#define S1_PERQ (D1*CH + CC*CH)                   // 1120
#define S1_SMEM ((S1_BASE + WQ*S1_PERQ) * 4)      // 49280 bytes

__global__ __launch_bounds__(32*WQ, 4) void stage1_kernel(
    const float* __restrict__ locs, const int* __restrict__ nbr,
    const float* __restrict__ w1a, const float* __restrict__ s1a, const float* __restrict__ t1a,
    const float* __restrict__ w1b, const float* __restrict__ s1b, const float* __restrict__ t1b)
{
    extern __shared__ float sm[];
    float* wa_s = sm;                 // D1*CC
    float* wb_s = wa_s + D1*CC;       // CC*HH
    float* ba_s = wb_s + CC*HH;       // CC
    float* bb_s = ba_s + CC;          // HH
    int tid  = threadIdx.x;
    int warp = tid >> 5;
    int lane = tid & 31;
    float* g1_s = sm + S1_BASE + warp * S1_PERQ;  // D1*CH
    float* h1_s = g1_s + D1*CH;                   // CC*CH

    int bs = blockIdx.x * WQ + warp;
    int b  = bs >> 10;

    for (int i = tid; i < D1 * CC; i += 32*WQ) wa_s[i] = w1a[i] * s1a[i & 31];
    for (int i = tid; i < CC * HH; i += 32*WQ) wb_s[i] = w1b[i] * s1b[i & 63];
    if (tid < CC) ba_s[tid] = t1a[tid];
    if (tid < HH) bb_s[tid] = t1b[tid];
    __syncthreads();   // only block barrier: weights visible

    int cgrp = lane & 7, ngrp = lane >> 3;   // 8 cgrps x 4 ngrps
    int n0 = ngrp * 4;
    int nb   = lane & 15;                    // staging: 2 threads per neighbor
    int half = lane >> 4;

    float qx = g_fps_locs[bs*3+0], qy = g_fps_locs[bs*3+1], qz = g_fps_locs[bs*3+2];
    float qdx = g_fps_dim[bs*3+0], qdy = g_fps_dim[bs*3+1], qdz = g_fps_dim[bs*3+2];

    float m[8];
    #pragma unroll
    for (int cc = 0; cc < 8; cc++) m[cc] = -3.4e38f;

    #pragma unroll 1
    for (int c = 0; c < NCHUNK; c++) {
        // ---- stage chunk c (warp-private) ----
        {
            int j = nbr[bs * KK + c * CH + nb];
            const float4* fp = (const float4*)(g_feats_nc + (((size_t)b * NN + j) << 5));
            if (half == 0) {
                const float* lp = locs + ((size_t)b * NN + j) * 3;
                g1_s[0*CH + nb] = (lp[0] - qx) * 2.5f;
                g1_s[1*CH + nb] = (lp[1] - qy) * 2.5f;
                g1_s[2*CH + nb] = (lp[2] - qz) * 2.5f;
                const float* dp = g_dimbox + ((size_t)b * NN + j) * 3;
                g1_s[3*CH + nb] = fabsf(dp[0] - qdx);
                g1_s[4*CH + nb] = fabsf(dp[1] - qdy);
                g1_s[5*CH + nb] = fabsf(dp[2] - qdz);
                #pragma unroll
                for (int qq = 0; qq < 4; qq++) {
                    float4 v = fp[qq];
                    g1_s[(6+4*qq+0)*CH + nb] = v.x;
                    g1_s[(6+4*qq+1)*CH + nb] = v.y;
                    g1_s[(6+4*qq+2)*CH + nb] = v.z;
                    g1_s[(6+4*qq+3)*CH + nb] = v.w;
                }
            } else {
                #pragma unroll
                for (int qq = 4; qq < 8; qq++) {
                    float4 v = fp[qq];
                    g1_s[(6+4*qq+0)*CH + nb] = v.x;
                    g1_s[(6+4*qq+1)*CH + nb] = v.y;
                    g1_s[(6+4*qq+2)*CH + nb] = v.z;
                    g1_s[(6+4*qq+3)*CH + nb] = v.w;
                }
            }
        }
        __syncwarp();

        // ---- GEMM A: 38 -> 32, relu. Tile 4n x 4c. ----
        {
            int c0 = cgrp * 4;
            ull acc[4][2];
            ull bi0 = pack2(ba_s[c0+0], ba_s[c0+1]);
            ull bi1 = pack2(ba_s[c0+2], ba_s[c0+3]);
            #pragma unroll
            for (int n = 0; n < 4; n++) { acc[n][0] = bi0; acc[n][1] = bi1; }

            #pragma unroll 2
            for (int i = 0; i < D1; i++) {
                float4 gv = *(const float4*)(g1_s + i * CH + n0);
                ulonglong2 wv = *(const ulonglong2*)(wa_s + i * CC + c0);
                ull gg[4] = { pack2(gv.x,gv.x), pack2(gv.y,gv.y), pack2(gv.z,gv.z), pack2(gv.w,gv.w) };
                #pragma unroll
                for (int n = 0; n < 4; n++) {
                    fma2(acc[n][0], gg[n], wv.x);
                    fma2(acc[n][1], gg[n], wv.y);
                }
            }
            __syncwarp();   // h1 readers of previous chunk done (loop back-edge safety)
            #pragma unroll
            for (int p = 0; p < 2; p++) {
                float lo[4], hi[4];
                #pragma unroll
                for (int n = 0; n < 4; n++) unpack2(acc[n][p], lo[n], hi[n]);
                *(float4*)(h1_s + (c0+2*p+0)*CH + n0) =
                    make_float4(fmaxf(lo[0],0.f), fmaxf(lo[1],0.f), fmaxf(lo[2],0.f), fmaxf(lo[3],0.f));
                *(float4*)(h1_s + (c0+2*p+1)*CH + n0) =
                    make_float4(fmaxf(hi[0],0.f), fmaxf(hi[1],0.f), fmaxf(hi[2],0.f), fmaxf(hi[3],0.f));
            }
        }
        __syncwarp();

        // ---- GEMM B: 32 -> 64, running max. Tile 4n x 8c. ----
        {
            int c0 = cgrp * 8;
            ull acc[4][4];
            #pragma unroll
            for (int p = 0; p < 4; p++) {
                ull bi = pack2(bb_s[c0+2*p], bb_s[c0+2*p+1]);
                #pragma unroll
                for (int n = 0; n < 4; n++) acc[n][p] = bi;
            }
            #pragma unroll 2
            for (int i = 0; i < CC; i++) {
                float4 gv = *(const float4*)(h1_s + i * CH + n0);
                ulonglong2 w0 = *(const ulonglong2*)(wb_s + i * HH + c0);
                ulonglong2 w1 = *(const ulonglong2*)(wb_s + i * HH + c0 + 4);
                ull wc[4] = { w0.x, w0.y, w1.x, w1.y };
                ull gg[4] = { pack2(gv.x,gv.x), pack2(gv.y,gv.y), pack2(gv.z,gv.z), pack2(gv.w,gv.w) };
                #pragma unroll
                for (int n = 0; n < 4; n++)
                    #pragma unroll
                    for (int p = 0; p < 4; p++) fma2(acc[n][p], gg[n], wc[p]);
            }
            #pragma unroll
            for (int p = 0; p < 4; p++)
                #pragma unroll
                for (int n = 0; n < 4; n++) {
                    float lo, hi; unpack2(acc[n][p], lo, hi);
                    m[2*p]   = fmaxf(m[2*p], lo);
                    m[2*p+1] = fmaxf(m[2*p+1], hi);
                }
        }
        __syncwarp();   // g1/h1 safe to overwrite next chunk
    }

    // reduce over 4 ngrps (lane bits 3,4), relu, store
    #pragma unroll
    for (int cc = 0; cc < 8; cc++) {
        m[cc] = fmaxf(m[cc], __shfl_xor_sync(0xffffffffu, m[cc], 8));
        m[cc] = fmaxf(m[cc], __shfl_xor_sync(0xffffffffu, m[cc], 16));
    }
    if (ngrp == 0) {
        int c0 = cgrp * 8;
        float4 v0 = make_float4(fmaxf(m[0],0.f), fmaxf(m[1],0.f), fmaxf(m[2],0.f), fmaxf(m[3],0.f));
        float4 v1 = make_float4(fmaxf(m[4],0.f), fmaxf(m[5],0.f), fmaxf(m[6],0.f), fmaxf(m[7],0.f));
        *(float4*)(g_newfeat + bs * HH + c0)     = v0;
        *(float4*)(g_newfeat + bs * HH + c0 + 4) = v1;
    }
}

// ================= stage 2: 1 warp per query, 4 chunks of 16 =============
// smem floats: w[4480] sb[64] | per-q: g[70*16]
#define S2_BASE (D2*HH + HH)                      // 4544
#define S2_PERQ (D2*CH)                           // 1120
#define S2_SMEM ((S2_BASE + WQ*S2_PERQ) * 4)      // 54016 bytes

__global__ __launch_bounds__(32*WQ, 4) void stage2_kernel(
    const int* __restrict__ nbr2,
    const float* __restrict__ w2, const float* __restrict__ s2, const float* __restrict__ t2)
{
    extern __shared__ float sm[];
    float* w_s = sm;                  // D2*HH
    float* sb  = w_s + D2*HH;         // HH
    int tid  = threadIdx.x;
    int warp = tid >> 5;
    int lane = tid & 31;
    float* g_s = sm + S2_BASE + warp * S2_PERQ;   // D2*CH

    int bs = blockIdx.x * WQ + warp;
    int b  = bs >> 10;

    for (int i = tid; i < D2 * HH; i += 32*WQ) w_s[i] = w2[i] * s2[i & 63];
    if (tid < HH) sb[tid] = t2[tid];
    __syncthreads();   // only block barrier

    int cgrp = lane & 7, ngrp = lane >> 3;
    int n0 = ngrp * 4, c0 = cgrp * 8;
    int nb   = lane & 15;
    int half = lane >> 4;

    float qx = g_fps_locs[bs*3+0], qy = g_fps_locs[bs*3+1], qz = g_fps_locs[bs*3+2];
    float qdx = g_fps_dim[bs*3+0], qdy = g_fps_dim[bs*3+1], qdz = g_fps_dim[bs*3+2];

    float m[8];
    #pragma unroll
    for (int cc = 0; cc < 8; cc++) m[cc] = -3.4e38f;

    #pragma unroll 1
    for (int c = 0; c < NCHUNK; c++) {
        // ---- stage chunk c (warp-private) ----
        {
            int j  = nbr2[bs * KK + c * CH + nb];
            int fj = (b << 10) + j;
            const float4* fp = (const float4*)(g_newfeat + (size_t)fj * HH);
            if (half == 0) {
                g_s[0*CH + nb] = (g_fps_locs[fj*3+0] - qx) * 1.25f;
                g_s[1*CH + nb] = (g_fps_locs[fj*3+1] - qy) * 1.25f;
                g_s[2*CH + nb] = (g_fps_locs[fj*3+2] - qz) * 1.25f;
                g_s[3*CH + nb] = fabsf(g_fps_dim[fj*3+0] - qdx);
                g_s[4*CH + nb] = fabsf(g_fps_dim[fj*3+1] - qdy);
                g_s[5*CH + nb] = fabsf(g_fps_dim[fj*3+2] - qdz);
                #pragma unroll
                for (int qq = 0; qq < 8; qq++) {
                    float4 v = fp[qq];
                    g_s[(6+4*qq+0)*CH + nb] = v.x;
                    g_s[(6+4*qq+1)*CH + nb] = v.y;
                    g_s[(6+4*qq+2)*CH + nb] = v.z;
                    g_s[(6+4*qq+3)*CH + nb] = v.w;
                }
            } else {
                #pragma unroll
                for (int qq = 8; qq < 16; qq++) {
                    float4 v = fp[qq];
                    g_s[(6+4*qq+0)*CH + nb] = v.x;
                    g_s[(6+4*qq+1)*CH + nb] = v.y;
                    g_s[(6+4*qq+2)*CH + nb] = v.z;
                    g_s[(6+4*qq+3)*CH + nb] = v.w;
                }
            }
        }
        __syncwarp();

        // ---- GEMM: 70 -> 64, running max. Tile 4n x 8c. ----
        {
            ull acc[4][4];
            #pragma unroll
            for (int p = 0; p < 4; p++) {
                ull bi = pack2(sb[c0+2*p], sb[c0+2*p+1]);
                #pragma unroll
                for (int n = 0; n < 4; n++) acc[n][p] = bi;
            }
            #pragma unroll 2
            for (int i = 0; i < D2; i++) {
                float4 gv = *(const float4*)(g_s + i * CH + n0);
                ulonglong2 w0 = *(const ulonglong2*)(w_s + i * HH + c0);
                ulonglong2 w1 = *(const ulonglong2*)(w_s + i * HH + c0 + 4);
                ull wc[4] = { w0.x, w0.y, w1.x, w1.y };
                ull gg[4] = { pack2(gv.x,gv.x), pack2(gv.y,gv.y), pack2(gv.z,gv.z), pack2(gv.w,gv.w) };
                #pragma unroll
                for (int n = 0; n < 4; n++)
                    #pragma unroll
                    for (int p = 0; p < 4; p++) fma2(acc[n][p], gg[n], wc[p]);
            }
            #pragma unroll
            for (int p = 0; p < 4; p++)
                #pragma unroll
                for (int n = 0; n < 4; n++) {
                    float lo, hi; unpack2(acc[n][p], lo, hi);
                    m[2*p]   = fmaxf(m[2*p], lo);
                    m[2*p+1] = fmaxf(m[2*p+1], hi);
                }
        }
        __syncwarp();
    }

    #pragma unroll
    for (int cc = 0; cc < 8; cc++) {
        m[cc] = fmaxf(m[cc], __shfl_xor_sync(0xffffffffu, m[cc], 8));
        m[cc] = fmaxf(m[cc], __shfl_xor_sync(0xffffffffu, m[cc], 16));
    }
    if (ngrp == 0) {
        *(float4*)(g_h2max + bs * HH + c0)     = make_float4(m[0], m[1], m[2], m[3]);
        *(float4*)(g_h2max + bs * HH + c0 + 4) = make_float4(m[4], m[5], m[6], m[7]);
    }
}

// ---------------- stage 3: bottleneck mlp3 + skip, write transposed ------
#define TS 16
__global__ __launch_bounds__(256) void stage3_kernel(
    const float* __restrict__ w3a, const float* __restrict__ s3a, const float* __restrict__ t3a,
    const float* __restrict__ w3b, const float* __restrict__ s3b, const float* __restrict__ t3b,
    float* __restrict__ out)
{
    __shared__ float h2s[TS * HH];
    __shared__ float h3s[TS * H3];
    int t = threadIdx.x;
    int row0 = blockIdx.x * TS;

    for (int i = t; i < TS * HH; i += 256) h2s[i] = g_h2max[row0 * HH + i];
    __syncthreads();

    {
        float sc = s3a[t], bi = t3a[t];
        float acc[TS];
        #pragma unroll
        for (int r = 0; r < TS; r++) acc[r] = bi;
        #pragma unroll 4
        for (int i = 0; i < HH; i++) {
            float wv = w3a[i * H3 + t] * sc;
            #pragma unroll
            for (int r = 0; r < TS; r++) acc[r] += h2s[r * HH + i] * wv;
        }
        #pragma unroll
        for (int r = 0; r < TS; r++) h3s[r * H3 + t] = fmaxf(acc[r], 0.0f);
    }
    __syncthreads();

    {
        int c  = t & 63;
        int rg = t >> 6;
        float sc = s3b[c], bi = t3b[c];
        float acc[4];
        #pragma unroll
        for (int rr = 0; rr < 4; rr++) acc[rr] = bi;
        #pragma unroll 4
        for (int i = 0; i < H3; i++) {
            float wv = w3b[i * HH + c] * sc;
            #pragma unroll
            for (int rr = 0; rr < 4; rr++)
                acc[rr] += h3s[(rg * 4 + rr) * H3 + i] * wv;
        }
        #pragma unroll
        for (int rr = 0; rr < 4; rr++) {
            int row = row0 + rg * 4 + rr;
            int b = row >> 10, s = row & 1023;
            float v = acc[rr] + g_newfeat[row * HH + c];
            out[OFF_OUT + ((b * HH + c) << 10) + s] = fmaxf(v, 0.0f);
        }
    }
}

// ---------------- launch ----------------
extern "C" void kernel_launch(void* const* d_in, const int* in_sizes, int n_in,
                              void* d_out, int out_size)
{
    const float* locs  = (const float*)d_in[0];
    const float* feats = (const float*)d_in[1];
    const float* boxes = (const float*)d_in[2];
    const int*   fps   = (const int*)d_in[3];
    const int*   nbr   = (const int*)d_in[4];
    const int*   nbr2  = (const int*)d_in[5];
    const float* w1a = (const float*)d_in[6];
    const float* s1a = (const float*)d_in[7];
    const float* t1a = (const float*)d_in[8];
    const float* w1b = (const float*)d_in[9];
    const float* s1b = (const float*)d_in[10];
    const float* t1b = (const float*)d_in[11];
    const float* w2  = (const float*)d_in[12];
    const float* s2  = (const float*)d_in[13];
    const float* t2  = (const float*)d_in[14];
    const float* w3a = (const float*)d_in[15];
    const float* s3a = (const float*)d_in[16];
    const float* t3a = (const float*)d_in[17];
    const float* w3b = (const float*)d_in[18];
    const float* s3b = (const float*)d_in[19];
    const float* t3b = (const float*)d_in[20];
    float* out = (float*)d_out;

    cudaFuncSetAttribute(stage1_kernel, cudaFuncAttributeMaxDynamicSharedMemorySize, S1_SMEM);
    cudaFuncSetAttribute(stage2_kernel, cudaFuncAttributeMaxDynamicSharedMemorySize, S2_SMEM);

    prep_kernel<<<(BB * NN + 255) / 256, 256>>>(feats, boxes);
    fps_kernel<<<(BB * SS + 255) / 256, 256>>>(locs, boxes, fps, out);
    stage1_kernel<<<BB * SS / WQ, 32*WQ, S1_SMEM>>>(locs, nbr, w1a, s1a, t1a, w1b, s1b, t1b);
    stage2_kernel<<<BB * SS / WQ, 32*WQ, S2_SMEM>>>(nbr2, w2, s2, t2);
    stage3_kernel<<<(BB * SS) / TS, 256>>>(w3a, s3a, t3a, w3b, s3b, t3b, out);
}

// round 12
// speedup vs baseline: 1.2350x; 1.2350x over previous
#include <cuda_runtime.h>
#include <cuda_bf16.h>

// ---------------- problem constants ----------------
#define BB 8
#define NN 131072
#define SS 1024
#define KK 64
#define CC 32
#define HH 64          // 2*C
#define D1 38          // C + 6
#define D2 70          // H + 6
#define H3 256         // 4*H

#define QPB 4          // queries per block (stage1/2)

// output layout (flattened concat of the 4 returned tensors)
#define OFF_LOCS  0
#define OFF_OUT   (BB*SS*3)                  // 24576
#define OFF_BOXES (OFF_OUT + BB*HH*SS)       // 548864
#define OFF_INDS  (OFF_BOXES + BB*SS*6)      // 598016

typedef unsigned long long ull;

// ---------------- f32x2 packed helpers (sm_100+) ----------------
__device__ __forceinline__ ull pack2(float lo, float hi) {
    ull r; asm("mov.b64 %0, {%1, %2};" : "=l"(r) : "f"(lo), "f"(hi)); return r;
}
__device__ __forceinline__ void unpack2(ull v, float& lo, float& hi) {
    asm("mov.b64 {%0, %1}, %2;" : "=f"(lo), "=f"(hi) : "l"(v));
}
__device__ __forceinline__ void fma2(ull& d, ull a, ull b) {
    asm("fma.rn.f32x2 %0, %1, %2, %0;" : "+l"(d) : "l"(a), "l"(b));
}

// ---------------- scratch (device globals; no allocation allowed) ----------
__device__ float g_feats_nc[BB * NN * CC];   // [B,N,C] transposed feats
__device__ float g_dimbox  [BB * NN * 3];
__device__ float g_fps_locs[BB * SS * 3];
__device__ float g_fps_dim [BB * SS * 3];
__device__ float g_newfeat [BB * SS * HH];   // stage1 output == identity
__device__ float g_h2max   [BB * SS * HH];   // stage2 output

// ---------------- prep: transpose feats, compute dim boxes ----------------
__global__ __launch_bounds__(256) void prep_kernel(
    const float* __restrict__ feats, const float* __restrict__ boxes)
{
    int idx = blockIdx.x * blockDim.x + threadIdx.x;   // over B*N
    if (idx >= BB * NN) return;
    int b = idx >> 17;
    int n = idx & (NN - 1);

    float tmp[CC];
    #pragma unroll
    for (int c = 0; c < CC; c++)
        tmp[c] = feats[(b * CC + c) * NN + n];

    float4* dst = (float4*)(g_feats_nc + ((size_t)idx << 5));
    #pragma unroll
    for (int q = 0; q < 8; q++)
        dst[q] = make_float4(tmp[4*q], tmp[4*q+1], tmp[4*q+2], tmp[4*q+3]);

    const float* bx = boxes + (size_t)idx * 6;
    float* dd = g_dimbox + (size_t)idx * 3;
    dd[0] = bx[3] - bx[0];
    dd[1] = bx[4] - bx[1];
    dd[2] = bx[5] - bx[2];
}

// ---------------- fps gather ----------
__global__ __launch_bounds__(256) void fps_kernel(
    const float* __restrict__ locs, const float* __restrict__ boxes,
    const int* __restrict__ fps_inds, float* __restrict__ out)
{
    int idx = blockIdx.x * blockDim.x + threadIdx.x;   // over B*S
    if (idx >= BB * SS) return;
    int b = idx >> 10;
    int j = fps_inds[idx];

    const float* lp = locs + ((size_t)b * NN + j) * 3;
    float l0 = lp[0], l1 = lp[1], l2 = lp[2];
    g_fps_locs[idx*3+0] = l0; g_fps_locs[idx*3+1] = l1; g_fps_locs[idx*3+2] = l2;
    out[OFF_LOCS + idx*3 + 0] = l0;
    out[OFF_LOCS + idx*3 + 1] = l1;
    out[OFF_LOCS + idx*3 + 2] = l2;

    const float* bx = boxes + ((size_t)b * NN + j) * 6;
    float b0 = bx[0], b1 = bx[1], b2 = bx[2], b3 = bx[3], b4 = bx[4], b5 = bx[5];
    g_fps_dim[idx*3+0] = b3 - b0;
    g_fps_dim[idx*3+1] = b4 - b1;
    g_fps_dim[idx*3+2] = b5 - b2;
    out[OFF_BOXES + idx*6 + 0] = b0;
    out[OFF_BOXES + idx*6 + 1] = b1;
    out[OFF_BOXES + idx*6 + 2] = b2;
    out[OFF_BOXES + idx*6 + 3] = b3;
    out[OFF_BOXES + idx*6 + 4] = b4;
    out[OFF_BOXES + idx*6 + 5] = b5;

    out[OFF_INDS + idx] = (float)j;
}

// ================= stage 1: QPB queries/block, shared weights ============
#define S1_BASE (D1*CC + CC*HH + CC + HH)       // 3360
#define S1_PERQ (D1*64 + CC*68 + 8*68)          // 5152
#define S1_SMEM ((S1_BASE + QPB*S1_PERQ) * 4)   // 95872 bytes

__global__ __launch_bounds__(64*QPB) void stage1_kernel(
    const float* __restrict__ locs, const int* __restrict__ nbr,
    const float* __restrict__ w1a, const float* __restrict__ s1a, const float* __restrict__ t1a,
    const float* __restrict__ w1b, const float* __restrict__ s1b, const float* __restrict__ t1b)
{
    extern __shared__ float sm[];
    float* wa_s = sm;                 // D1*CC
    float* wb_s = wa_s + D1*CC;       // CC*HH
    float* ba_s = wb_s + CC*HH;       // CC
    float* bb_s = ba_s + CC;          // HH
    int tid  = threadIdx.x;
    int q    = tid >> 6;
    int ltid = tid & 63;
    float* g1_s = sm + S1_BASE + q * S1_PERQ;   // D1*64
    float* h1_s = g1_s + D1*64;                 // CC*68
    float* red  = h1_s + CC*68;                 // 8*68

    int bs = blockIdx.x * QPB + q;
    int b  = bs >> 10;

    for (int i = tid; i < D1 * CC; i += 64*QPB) wa_s[i] = w1a[i] * s1a[i & 31];
    for (int i = tid; i < CC * HH; i += 64*QPB) wb_s[i] = w1b[i] * s1b[i & 63];
    if (tid < CC) ba_s[tid] = t1a[tid];
    if (tid < HH) bb_s[tid] = t1b[tid];

    // ---- fill g1_s[i][n]: thread = neighbor ----
    {
        int j = nbr[bs * KK + ltid];
        const float* lp = locs + ((size_t)b * NN + j) * 3;
        g1_s[0*64 + ltid] = (lp[0] - g_fps_locs[bs*3+0]) * 2.5f;
        g1_s[1*64 + ltid] = (lp[1] - g_fps_locs[bs*3+1]) * 2.5f;
        g1_s[2*64 + ltid] = (lp[2] - g_fps_locs[bs*3+2]) * 2.5f;
        const float* dp = g_dimbox + ((size_t)b * NN + j) * 3;
        g1_s[3*64 + ltid] = fabsf(dp[0] - g_fps_dim[bs*3+0]);
        g1_s[4*64 + ltid] = fabsf(dp[1] - g_fps_dim[bs*3+1]);
        g1_s[5*64 + ltid] = fabsf(dp[2] - g_fps_dim[bs*3+2]);
        const float4* fp = (const float4*)(g_feats_nc + (((size_t)b * NN + j) << 5));
        #pragma unroll
        for (int qq = 0; qq < 8; qq++) {
            float4 v = fp[qq];
            g1_s[(6+4*qq+0)*64 + ltid] = v.x;
            g1_s[(6+4*qq+1)*64 + ltid] = v.y;
            g1_s[(6+4*qq+2)*64 + ltid] = v.z;
            g1_s[(6+4*qq+3)*64 + ltid] = v.w;
        }
    }
    __syncthreads();

    int ngrp = ltid & 7, cgrp = ltid >> 3;
    int n0 = ngrp * 8;

    // ---- GEMM A: 38 -> 32, relu. Tile 8n x 4c, prefetched. ----
    {
        int c0 = cgrp * 4;
        ull acc[8][2];
        ull bi0 = pack2(ba_s[c0+0], ba_s[c0+1]);
        ull bi1 = pack2(ba_s[c0+2], ba_s[c0+3]);
        #pragma unroll
        for (int n = 0; n < 8; n++) { acc[n][0] = bi0; acc[n][1] = bi1; }

        float4 ga = *(const float4*)(g1_s + n0);
        float4 gb = *(const float4*)(g1_s + n0 + 4);
        ulonglong2 wv = *(const ulonglong2*)(wa_s + c0);
        #pragma unroll 2
        for (int i = 0; i < D1; i++) {
            float4 nga, ngb; ulonglong2 nwv;
            if (i < D1 - 1) {
                nga = *(const float4*)(g1_s + (i+1) * 64 + n0);
                ngb = *(const float4*)(g1_s + (i+1) * 64 + n0 + 4);
                nwv = *(const ulonglong2*)(wa_s + (i+1) * CC + c0);
            }
            ull g2[8] = { pack2(ga.x,ga.x), pack2(ga.y,ga.y), pack2(ga.z,ga.z), pack2(ga.w,ga.w),
                          pack2(gb.x,gb.x), pack2(gb.y,gb.y), pack2(gb.z,gb.z), pack2(gb.w,gb.w) };
            #pragma unroll
            for (int n = 0; n < 8; n++) {
                fma2(acc[n][0], g2[n], wv.x);
                fma2(acc[n][1], g2[n], wv.y);
            }
            ga = nga; gb = ngb; wv = nwv;
        }
        #pragma unroll
        for (int n = 0; n < 8; n++) {
            float v0, v1, v2, v3;
            unpack2(acc[n][0], v0, v1);
            unpack2(acc[n][1], v2, v3);
            h1_s[(c0+0)*68 + n0 + n] = fmaxf(v0, 0.0f);
            h1_s[(c0+1)*68 + n0 + n] = fmaxf(v1, 0.0f);
            h1_s[(c0+2)*68 + n0 + n] = fmaxf(v2, 0.0f);
            h1_s[(c0+3)*68 + n0 + n] = fmaxf(v3, 0.0f);
        }
    }
    __syncthreads();

    // ---- GEMM B: 32 -> 64, relu, max over K. Tile 8n x 8c, prefetched. ----
    {
        int c0 = cgrp * 8;
        ull acc[8][4];
        ull bi[4];
        #pragma unroll
        for (int p = 0; p < 4; p++) bi[p] = pack2(bb_s[c0+2*p], bb_s[c0+2*p+1]);
        #pragma unroll
        for (int n = 0; n < 8; n++)
            #pragma unroll
            for (int p = 0; p < 4; p++) acc[n][p] = bi[p];

        float4 ga = *(const float4*)(h1_s + n0);
        float4 gb = *(const float4*)(h1_s + n0 + 4);
        ulonglong2 wv0 = *(const ulonglong2*)(wb_s + c0);
        ulonglong2 wv1 = *(const ulonglong2*)(wb_s + c0 + 4);
        #pragma unroll 2
        for (int i = 0; i < CC; i++) {
            float4 nga, ngb; ulonglong2 nw0, nw1;
            if (i < CC - 1) {
                nga = *(const float4*)(h1_s + (i+1) * 68 + n0);
                ngb = *(const float4*)(h1_s + (i+1) * 68 + n0 + 4);
                nw0 = *(const ulonglong2*)(wb_s + (i+1) * HH + c0);
                nw1 = *(const ulonglong2*)(wb_s + (i+1) * HH + c0 + 4);
            }
            ull w[4] = { wv0.x, wv0.y, wv1.x, wv1.y };
            ull g2[8] = { pack2(ga.x,ga.x), pack2(ga.y,ga.y), pack2(ga.z,ga.z), pack2(ga.w,ga.w),
                          pack2(gb.x,gb.x), pack2(gb.y,gb.y), pack2(gb.z,gb.z), pack2(gb.w,gb.w) };
            #pragma unroll
            for (int n = 0; n < 8; n++)
                #pragma unroll
                for (int p = 0; p < 4; p++) fma2(acc[n][p], g2[n], w[p]);
            ga = nga; gb = ngb; wv0 = nw0; wv1 = nw1;
        }

        // local max over the 8 register-resident neighbors (relu deferred: monotone)
        float m[8];
        #pragma unroll
        for (int p = 0; p < 4; p++) unpack2(acc[0][p], m[2*p], m[2*p+1]);
        #pragma unroll
        for (int n = 1; n < 8; n++)
            #pragma unroll
            for (int p = 0; p < 4; p++) {
                float lo, hi; unpack2(acc[n][p], lo, hi);
                m[2*p]   = fmaxf(m[2*p], lo);
                m[2*p+1] = fmaxf(m[2*p+1], hi);
            }
        #pragma unroll
        for (int j = 0; j < 8; j++) red[ngrp * 68 + c0 + j] = m[j];
    }
    __syncthreads();

    float mm = red[ltid];
    #pragma unroll
    for (int r = 1; r < 8; r++) mm = fmaxf(mm, red[r * 68 + ltid]);
    g_newfeat[bs * HH + ltid] = fmaxf(mm, 0.0f);
}

// ================= stage 2: QPB queries/block, shared weights ============
#define S2_BASE (D2*HH + HH)                    // 4544
#define S2_PERQ (D2*64 + 8*68)                  // 5024
#define S2_SMEM ((S2_BASE + QPB*S2_PERQ) * 4)   // 98560 bytes

__global__ __launch_bounds__(64*QPB) void stage2_kernel(
    const int* __restrict__ nbr2,
    const float* __restrict__ w2, const float* __restrict__ s2, const float* __restrict__ t2)
{
    extern __shared__ float sm[];
    float* w_s = sm;                  // D2*HH
    float* sb  = w_s + D2*HH;         // HH
    int tid  = threadIdx.x;
    int q    = tid >> 6;
    int ltid = tid & 63;
    float* g_s = sm + S2_BASE + q * S2_PERQ;   // D2*64
    float* red = g_s + D2*64;                  // 8*68

    int bs = blockIdx.x * QPB + q;
    int b  = bs >> 10;

    for (int i = tid; i < D2 * HH; i += 64*QPB) w_s[i] = w2[i] * s2[i & 63];
    if (tid < HH) sb[tid] = t2[tid];

    // ---- fill g_s[i][n]: thread = neighbor ----
    {
        int j  = nbr2[bs * KK + ltid];
        int fj = (b << 10) + j;
        g_s[0*64 + ltid] = (g_fps_locs[fj*3+0] - g_fps_locs[bs*3+0]) * 1.25f;
        g_s[1*64 + ltid] = (g_fps_locs[fj*3+1] - g_fps_locs[bs*3+1]) * 1.25f;
        g_s[2*64 + ltid] = (g_fps_locs[fj*3+2] - g_fps_locs[bs*3+2]) * 1.25f;
        g_s[3*64 + ltid] = fabsf(g_fps_dim[fj*3+0] - g_fps_dim[bs*3+0]);
        g_s[4*64 + ltid] = fabsf(g_fps_dim[fj*3+1] - g_fps_dim[bs*3+1]);
        g_s[5*64 + ltid] = fabsf(g_fps_dim[fj*3+2] - g_fps_dim[bs*3+2]);
        const float4* fp = (const float4*)(g_newfeat + (size_t)fj * HH);
        #pragma unroll
        for (int qq = 0; qq < 16; qq++) {
            float4 v = fp[qq];
            g_s[(6+4*qq+0)*64 + ltid] = v.x;
            g_s[(6+4*qq+1)*64 + ltid] = v.y;
            g_s[(6+4*qq+2)*64 + ltid] = v.z;
            g_s[(6+4*qq+3)*64 + ltid] = v.w;
        }
    }
    __syncthreads();

    int ngrp = ltid & 7, cgrp = ltid >> 3;
    int n0 = ngrp * 8, c0 = cgrp * 8;

    ull acc[8][4];
    {
        ull bi[4];
        #pragma unroll
        for (int p = 0; p < 4; p++) bi[p] = pack2(sb[c0+2*p], sb[c0+2*p+1]);
        #pragma unroll
        for (int n = 0; n < 8; n++)
            #pragma unroll
            for (int p = 0; p < 4; p++) acc[n][p] = bi[p];
    }

    float4 ga = *(const float4*)(g_s + n0);
    float4 gb = *(const float4*)(g_s + n0 + 4);
    ulonglong2 wv0 = *(const ulonglong2*)(w_s + c0);
    ulonglong2 wv1 = *(const ulonglong2*)(w_s + c0 + 4);
    #pragma unroll 2
    for (int i = 0; i < D2; i++) {
        float4 nga, ngb; ulonglong2 nw0, nw1;
        if (i < D2 - 1) {
            nga = *(const float4*)(g_s + (i+1) * 64 + n0);
            ngb = *(const float4*)(g_s + (i+1) * 64 + n0 + 4);
            nw0 = *(const ulonglong2*)(w_s + (i+1) * HH + c0);
            nw1 = *(const ulonglong2*)(w_s + (i+1) * HH + c0 + 4);
        }
        ull w[4] = { wv0.x, wv0.y, wv1.x, wv1.y };
        ull g2[8] = { pack2(ga.x,ga.x), pack2(ga.y,ga.y), pack2(ga.z,ga.z), pack2(ga.w,ga.w),
                      pack2(gb.x,gb.x), pack2(gb.y,gb.y), pack2(gb.z,gb.z), pack2(gb.w,gb.w) };
        #pragma unroll
        for (int n = 0; n < 8; n++)
            #pragma unroll
            for (int p = 0; p < 4; p++) fma2(acc[n][p], g2[n], w[p]);
        ga = nga; gb = ngb; wv0 = nw0; wv1 = nw1;
    }

    // max over 8 local neighbors (no relu in stage 2)
    float m[8];
    #pragma unroll
    for (int p = 0; p < 4; p++) unpack2(acc[0][p], m[2*p], m[2*p+1]);
    #pragma unroll
    for (int n = 1; n < 8; n++)
        #pragma unroll
        for (int p = 0; p < 4; p++) {
            float lo, hi; unpack2(acc[n][p], lo, hi);
            m[2*p]   = fmaxf(m[2*p], lo);
            m[2*p+1] = fmaxf(m[2*p+1], hi);
        }
    #pragma unroll
    for (int j = 0; j < 8; j++) red[ngrp * 68 + c0 + j] = m[j];
    __syncthreads();

    float mm = red[ltid];
    #pragma unroll
    for (int r = 1; r < 8; r++) mm = fmaxf(mm, red[r * 68 + ltid]);
    g_h2max[bs * HH + ltid] = mm;
}

// ---------------- stage 3: bottleneck mlp3 + skip, write transposed ------
#define TS 16
__global__ __launch_bounds__(256) void stage3_kernel(
    const float* __restrict__ w3a, const float* __restrict__ s3a, const float* __restrict__ t3a,
    const float* __restrict__ w3b, const float* __restrict__ s3b, const float* __restrict__ t3b,
    float* __restrict__ out)
{
    __shared__ float h2s[TS * HH];
    __shared__ float h3s[TS * H3];
    int t = threadIdx.x;
    int row0 = blockIdx.x * TS;

    for (int i = t; i < TS * HH; i += 256) h2s[i] = g_h2max[row0 * HH + i];
    __syncthreads();

    {
        float sc = s3a[t], bi = t3a[t];
        float acc[TS];
        #pragma unroll
        for (int r = 0; r < TS; r++) acc[r] = bi;
        #pragma unroll 4
        for (int i = 0; i < HH; i++) {
            float wv = w3a[i * H3 + t] * sc;
            #pragma unroll
            for (int r = 0; r < TS; r++) acc[r] += h2s[r * HH + i] * wv;
        }
        #pragma unroll
        for (int r = 0; r < TS; r++) h3s[r * H3 + t] = fmaxf(acc[r], 0.0f);
    }
    __syncthreads();

    {
        int c  = t & 63;
        int rg = t >> 6;
        float sc = s3b[c], bi = t3b[c];
        float acc[4];
        #pragma unroll
        for (int rr = 0; rr < 4; rr++) acc[rr] = bi;
        #pragma unroll 4
        for (int i = 0; i < H3; i++) {
            float wv = w3b[i * HH + c] * sc;
            #pragma unroll
            for (int rr = 0; rr < 4; rr++)
                acc[rr] += h3s[(rg * 4 + rr) * H3 + i] * wv;
        }
        #pragma unroll
        for (int rr = 0; rr < 4; rr++) {
            int row = row0 + rg * 4 + rr;
            int b = row >> 10, s = row & 1023;
            float v = acc[rr] + g_newfeat[row * HH + c];
            out[OFF_OUT + ((b * HH + c) << 10) + s] = fmaxf(v, 0.0f);
        }
    }
}

// ---------------- launch ----------------
extern "C" void kernel_launch(void* const* d_in, const int* in_sizes, int n_in,
                              void* d_out, int out_size)
{
    const float* locs  = (const float*)d_in[0];
    const float* feats = (const float*)d_in[1];
    const float* boxes = (const float*)d_in[2];
    const int*   fps   = (const int*)d_in[3];
    const int*   nbr   = (const int*)d_in[4];
    const int*   nbr2  = (const int*)d_in[5];
    const float* w1a = (const float*)d_in[6];
    const float* s1a = (const float*)d_in[7];
    const float* t1a = (const float*)d_in[8];
    const float* w1b = (const float*)d_in[9];
    const float* s1b = (const float*)d_in[10];
    const float* t1b = (const float*)d_in[11];
    const float* w2  = (const float*)d_in[12];
    const float* s2  = (const float*)d_in[13];
    const float* t2  = (const float*)d_in[14];
    const float* w3a = (const float*)d_in[15];
    const float* s3a = (const float*)d_in[16];
    const float* t3a = (const float*)d_in[17];
    const float* w3b = (const float*)d_in[18];
    const float* s3b = (const float*)d_in[19];
    const float* t3b = (const float*)d_in[20];
    float* out = (float*)d_out;

    cudaFuncSetAttribute(stage1_kernel, cudaFuncAttributeMaxDynamicSharedMemorySize, S1_SMEM);
    cudaFuncSetAttribute(stage2_kernel, cudaFuncAttributeMaxDynamicSharedMemorySize, S2_SMEM);

    prep_kernel<<<(BB * NN + 255) / 256, 256>>>(feats, boxes);
    fps_kernel<<<(BB * SS + 255) / 256, 256>>>(locs, boxes, fps, out);
    stage1_kernel<<<BB * SS / QPB, 64*QPB, S1_SMEM>>>(locs, nbr, w1a, s1a, t1a, w1b, s1b, t1b);
    stage2_kernel<<<BB * SS / QPB, 64*QPB, S2_SMEM>>>(nbr2, w2, s2, t2);
    stage3_kernel<<<(BB * SS) / TS, 256>>>(w3a, s3a, t3a, w3b, s3b, t3b, out);
}

// round 14
// speedup vs baseline: 1.3517x; 1.0944x over previous
#include <cuda_runtime.h>
#include <cuda_bf16.h>
#include <cuda_fp16.h>
#include <cstdint>

// ---------------- problem constants ----------------
#define BB 8
#define NN 131072
#define SS 1024
#define KK 64
#define CC 32
#define HH 64          // 2*C
#define D1 38          // C + 6
#define D2 70          // H + 6
#define H3 256         // 4*H

#define QPB 4          // queries per block (stage1)

// output layout (flattened concat of the 4 returned tensors)
#define OFF_LOCS  0
#define OFF_OUT   (BB*SS*3)                  // 24576
#define OFF_BOXES (OFF_OUT + BB*HH*SS)       // 548864
#define OFF_INDS  (OFF_BOXES + BB*SS*6)      // 598016

typedef unsigned long long ull;

// ---------------- f32x2 packed helpers (sm_100+) ----------------
__device__ __forceinline__ ull pack2(float lo, float hi) {
    ull r; asm("mov.b64 %0, {%1, %2};" : "=l"(r) : "f"(lo), "f"(hi)); return r;
}
__device__ __forceinline__ void unpack2(ull v, float& lo, float& hi) {
    asm("mov.b64 {%0, %1}, %2;" : "=f"(lo), "=f"(hi) : "l"(v));
}
__device__ __forceinline__ void fma2(ull& d, ull a, ull b) {
    asm("fma.rn.f32x2 %0, %1, %2, %0;" : "+l"(d) : "l"(a), "l"(b));
}

// ---------------- scratch (device globals; no allocation allowed) ----------
__device__ float g_feats_nc[BB * NN * CC];   // [B,N,C] transposed feats
__device__ float g_dimbox  [BB * NN * 3];
__device__ float g_fps_locs[BB * SS * 3];
__device__ float g_fps_dim [BB * SS * 3];
__device__ float g_newfeat [BB * SS * HH];   // stage1 output == identity
__device__ float g_h2max   [BB * SS * HH];   // stage2 output

// ---------------- prep: transpose feats, compute dim boxes ----------------
__global__ __launch_bounds__(256) void prep_kernel(
    const float* __restrict__ feats, const float* __restrict__ boxes)
{
    int idx = blockIdx.x * blockDim.x + threadIdx.x;   // over B*N
    if (idx >= BB * NN) return;
    int b = idx >> 17;
    int n = idx & (NN - 1);

    float tmp[CC];
    #pragma unroll
    for (int c = 0; c < CC; c++)
        tmp[c] = feats[(b * CC + c) * NN + n];

    float4* dst = (float4*)(g_feats_nc + ((size_t)idx << 5));
    #pragma unroll
    for (int q = 0; q < 8; q++)
        dst[q] = make_float4(tmp[4*q], tmp[4*q+1], tmp[4*q+2], tmp[4*q+3]);

    const float* bx = boxes + (size_t)idx * 6;
    float* dd = g_dimbox + (size_t)idx * 3;
    dd[0] = bx[3] - bx[0];
    dd[1] = bx[4] - bx[1];
    dd[2] = bx[5] - bx[2];
}

// ---------------- fps gather ----------
__global__ __launch_bounds__(256) void fps_kernel(
    const float* __restrict__ locs, const float* __restrict__ boxes,
    const int* __restrict__ fps_inds, float* __restrict__ out)
{
    int idx = blockIdx.x * blockDim.x + threadIdx.x;   // over B*S
    if (idx >= BB * SS) return;
    int b = idx >> 10;
    int j = fps_inds[idx];

    const float* lp = locs + ((size_t)b * NN + j) * 3;
    float l0 = lp[0], l1 = lp[1], l2 = lp[2];
    g_fps_locs[idx*3+0] = l0; g_fps_locs[idx*3+1] = l1; g_fps_locs[idx*3+2] = l2;
    out[OFF_LOCS + idx*3 + 0] = l0;
    out[OFF_LOCS + idx*3 + 1] = l1;
    out[OFF_LOCS + idx*3 + 2] = l2;

    const float* bx = boxes + ((size_t)b * NN + j) * 6;
    float b0 = bx[0], b1 = bx[1], b2 = bx[2], b3 = bx[3], b4 = bx[4], b5 = bx[5];
    g_fps_dim[idx*3+0] = b3 - b0;
    g_fps_dim[idx*3+1] = b4 - b1;
    g_fps_dim[idx*3+2] = b5 - b2;
    out[OFF_BOXES + idx*6 + 0] = b0;
    out[OFF_BOXES + idx*6 + 1] = b1;
    out[OFF_BOXES + idx*6 + 2] = b2;
    out[OFF_BOXES + idx*6 + 3] = b3;
    out[OFF_BOXES + idx*6 + 4] = b4;
    out[OFF_BOXES + idx*6 + 5] = b5;

    out[OFF_INDS + idx] = (float)j;
}

// ================= stage 1: QPB queries/block, shared weights (R12) ======
#define S1_BASE (D1*CC + CC*HH + CC + HH)       // 3360
#define S1_PERQ (D1*64 + CC*68 + 8*68)          // 5152
#define S1_SMEM ((S1_BASE + QPB*S1_PERQ) * 4)   // 95872 bytes

__global__ __launch_bounds__(64*QPB) void stage1_kernel(
    const float* __restrict__ locs, const int* __restrict__ nbr,
    const float* __restrict__ w1a, const float* __restrict__ s1a, const float* __restrict__ t1a,
    const float* __restrict__ w1b, const float* __restrict__ s1b, const float* __restrict__ t1b)
{
    extern __shared__ float sm[];
    float* wa_s = sm;                 // D1*CC
    float* wb_s = wa_s + D1*CC;       // CC*HH
    float* ba_s = wb_s + CC*HH;       // CC
    float* bb_s = ba_s + CC;          // HH
    int tid  = threadIdx.x;
    int q    = tid >> 6;
    int ltid = tid & 63;
    float* g1_s = sm + S1_BASE + q * S1_PERQ;   // D1*64
    float* h1_s = g1_s + D1*64;                 // CC*68
    float* red  = h1_s + CC*68;                 // 8*68

    int bs = blockIdx.x * QPB + q;
    int b  = bs >> 10;

    for (int i = tid; i < D1 * CC; i += 64*QPB) wa_s[i] = w1a[i] * s1a[i & 31];
    for (int i = tid; i < CC * HH; i += 64*QPB) wb_s[i] = w1b[i] * s1b[i & 63];
    if (tid < CC) ba_s[tid] = t1a[tid];
    if (tid < HH) bb_s[tid] = t1b[tid];

    // ---- fill g1_s[i][n]: thread = neighbor ----
    {
        int j = nbr[bs * KK + ltid];
        const float* lp = locs + ((size_t)b * NN + j) * 3;
        g1_s[0*64 + ltid] = (lp[0] - g_fps_locs[bs*3+0]) * 2.5f;
        g1_s[1*64 + ltid] = (lp[1] - g_fps_locs[bs*3+1]) * 2.5f;
        g1_s[2*64 + ltid] = (lp[2] - g_fps_locs[bs*3+2]) * 2.5f;
        const float* dp = g_dimbox + ((size_t)b * NN + j) * 3;
        g1_s[3*64 + ltid] = fabsf(dp[0] - g_fps_dim[bs*3+0]);
        g1_s[4*64 + ltid] = fabsf(dp[1] - g_fps_dim[bs*3+1]);
        g1_s[5*64 + ltid] = fabsf(dp[2] - g_fps_dim[bs*3+2]);
        const float4* fp = (const float4*)(g_feats_nc + (((size_t)b * NN + j) << 5));
        #pragma unroll
        for (int qq = 0; qq < 8; qq++) {
            float4 v = fp[qq];
            g1_s[(6+4*qq+0)*64 + ltid] = v.x;
            g1_s[(6+4*qq+1)*64 + ltid] = v.y;
            g1_s[(6+4*qq+2)*64 + ltid] = v.z;
            g1_s[(6+4*qq+3)*64 + ltid] = v.w;
        }
    }
    __syncthreads();

    int ngrp = ltid & 7, cgrp = ltid >> 3;
    int n0 = ngrp * 8;

    // ---- GEMM A: 38 -> 32, relu. Tile 8n x 4c, prefetched. ----
    {
        int c0 = cgrp * 4;
        ull acc[8][2];
        ull bi0 = pack2(ba_s[c0+0], ba_s[c0+1]);
        ull bi1 = pack2(ba_s[c0+2], ba_s[c0+3]);
        #pragma unroll
        for (int n = 0; n < 8; n++) { acc[n][0] = bi0; acc[n][1] = bi1; }

        float4 ga = *(const float4*)(g1_s + n0);
        float4 gb = *(const float4*)(g1_s + n0 + 4);
        ulonglong2 wv = *(const ulonglong2*)(wa_s + c0);
        #pragma unroll 2
        for (int i = 0; i < D1; i++) {
            float4 nga, ngb; ulonglong2 nwv;
            if (i < D1 - 1) {
                nga = *(const float4*)(g1_s + (i+1) * 64 + n0);
                ngb = *(const float4*)(g1_s + (i+1) * 64 + n0 + 4);
                nwv = *(const ulonglong2*)(wa_s + (i+1) * CC + c0);
            }
            ull g2[8] = { pack2(ga.x,ga.x), pack2(ga.y,ga.y), pack2(ga.z,ga.z), pack2(ga.w,ga.w),
                          pack2(gb.x,gb.x), pack2(gb.y,gb.y), pack2(gb.z,gb.z), pack2(gb.w,gb.w) };
            #pragma unroll
            for (int n = 0; n < 8; n++) {
                fma2(acc[n][0], g2[n], wv.x);
                fma2(acc[n][1], g2[n], wv.y);
            }
            ga = nga; gb = ngb; wv = nwv;
        }
        #pragma unroll
        for (int n = 0; n < 8; n++) {
            float v0, v1, v2, v3;
            unpack2(acc[n][0], v0, v1);
            unpack2(acc[n][1], v2, v3);
            h1_s[(c0+0)*68 + n0 + n] = fmaxf(v0, 0.0f);
            h1_s[(c0+1)*68 + n0 + n] = fmaxf(v1, 0.0f);
            h1_s[(c0+2)*68 + n0 + n] = fmaxf(v2, 0.0f);
            h1_s[(c0+3)*68 + n0 + n] = fmaxf(v3, 0.0f);
        }
    }
    __syncthreads();

    // ---- GEMM B: 32 -> 64, relu, max over K. Tile 8n x 8c, prefetched. ----
    {
        int c0 = cgrp * 8;
        ull acc[8][4];
        ull bi[4];
        #pragma unroll
        for (int p = 0; p < 4; p++) bi[p] = pack2(bb_s[c0+2*p], bb_s[c0+2*p+1]);
        #pragma unroll
        for (int n = 0; n < 8; n++)
            #pragma unroll
            for (int p = 0; p < 4; p++) acc[n][p] = bi[p];

        float4 ga = *(const float4*)(h1_s + n0);
        float4 gb = *(const float4*)(h1_s + n0 + 4);
        ulonglong2 wv0 = *(const ulonglong2*)(wb_s + c0);
        ulonglong2 wv1 = *(const ulonglong2*)(wb_s + c0 + 4);
        #pragma unroll 2
        for (int i = 0; i < CC; i++) {
            float4 nga, ngb; ulonglong2 nw0, nw1;
            if (i < CC - 1) {
                nga = *(const float4*)(h1_s + (i+1) * 68 + n0);
                ngb = *(const float4*)(h1_s + (i+1) * 68 + n0 + 4);
                nw0 = *(const ulonglong2*)(wb_s + (i+1) * HH + c0);
                nw1 = *(const ulonglong2*)(wb_s + (i+1) * HH + c0 + 4);
            }
            ull w[4] = { wv0.x, wv0.y, wv1.x, wv1.y };
            ull g2[8] = { pack2(ga.x,ga.x), pack2(ga.y,ga.y), pack2(ga.z,ga.z), pack2(ga.w,ga.w),
                          pack2(gb.x,gb.x), pack2(gb.y,gb.y), pack2(gb.z,gb.z), pack2(gb.w,gb.w) };
            #pragma unroll
            for (int n = 0; n < 8; n++)
                #pragma unroll
                for (int p = 0; p < 4; p++) fma2(acc[n][p], g2[n], w[p]);
            ga = nga; gb = ngb; wv0 = nw0; wv1 = nw1;
        }

        float m[8];
        #pragma unroll
        for (int p = 0; p < 4; p++) unpack2(acc[0][p], m[2*p], m[2*p+1]);
        #pragma unroll
        for (int n = 1; n < 8; n++)
            #pragma unroll
            for (int p = 0; p < 4; p++) {
                float lo, hi; unpack2(acc[n][p], lo, hi);
                m[2*p]   = fmaxf(m[2*p], lo);
                m[2*p+1] = fmaxf(m[2*p+1], hi);
            }
        #pragma unroll
        for (int j = 0; j < 8; j++) red[ngrp * 68 + c0 + j] = m[j];
    }
    __syncthreads();

    float mm = red[ltid];
    #pragma unroll
    for (int r = 1; r < 8; r++) mm = fmaxf(mm, red[r * 68 + ltid]);
    g_newfeat[bs * HH + ltid] = fmaxf(mm, 0.0f);
}

// ================= stage 2: warp-level HMMA (mma.sync m16n8k16 fp16) =====
// One warp = one query. D[64n x 64c] = A[64x80] @ B[64x80]^T, fp32 accum.
// smem (halves): B [64ch][88] shared | per-warp A [64nbr][88]
#define S2H_STRIDE 88
#define S2H_TILE   (64 * S2H_STRIDE)                 // 5632 halves = 11264 B
#define S2H_SMEM   ((S2H_TILE * 9) * 2)              // 101376 bytes

__device__ __forceinline__ void mma16816(
    float* d, uint32_t a0, uint32_t a1, uint32_t a2, uint32_t a3,
    uint32_t b0, uint32_t b1)
{
    asm volatile(
        "mma.sync.aligned.m16n8k16.row.col.f32.f16.f16.f32 "
        "{%0,%1,%2,%3}, {%4,%5,%6,%7}, {%8,%9}, {%0,%1,%2,%3};"
        : "+f"(d[0]), "+f"(d[1]), "+f"(d[2]), "+f"(d[3])
        : "r"(a0), "r"(a1), "r"(a2), "r"(a3), "r"(b0), "r"(b1));
}

__global__ __launch_bounds__(256, 2) void stage2_mma_kernel(
    const int* __restrict__ nbr2,
    const float* __restrict__ w2, const float* __restrict__ s2, const float* __restrict__ t2)
{
    extern __shared__ __half hsm[];
    __half* Bs = hsm;                         // [n=64][k 0..79], stride 88
    int tid  = threadIdx.x;
    int warp = tid >> 5;
    int lane = tid & 31;
    __half* As = hsm + S2H_TILE * (1 + warp); // [nbr=64][k 0..79], stride 88

    int bs = blockIdx.x * 8 + warp;
    int b  = bs >> 10;

    // ---- stage B (folded weights, fp16) cooperatively; k>=70 zero-padded ----
    for (int idx = tid; idx < 64 * 80; idx += 256) {
        int n = idx / 80, k = idx % 80;
        float v = (k < D2) ? w2[k * HH + n] * s2[n] : 0.0f;
        Bs[n * S2H_STRIDE + k] = __float2half(v);
    }

    // ---- stage A: lane handles neighbors lane and lane+32 ----
    #pragma unroll
    for (int rr = 0; rr < 2; rr++) {
        int nb = lane + rr * 32;
        int j  = nbr2[bs * KK + nb];
        int fj = (b << 10) + j;
        __half* row = As + nb * S2H_STRIDE;

        float gx = (g_fps_locs[fj*3+0] - g_fps_locs[bs*3+0]) * 1.25f;
        float gy = (g_fps_locs[fj*3+1] - g_fps_locs[bs*3+1]) * 1.25f;
        float gz = (g_fps_locs[fj*3+2] - g_fps_locs[bs*3+2]) * 1.25f;
        float dx = fabsf(g_fps_dim[fj*3+0] - g_fps_dim[bs*3+0]);
        float dy = fabsf(g_fps_dim[fj*3+1] - g_fps_dim[bs*3+1]);
        float dz = fabsf(g_fps_dim[fj*3+2] - g_fps_dim[bs*3+2]);
        *(__half2*)(row + 0) = __floats2half2_rn(gx, gy);
        *(__half2*)(row + 2) = __floats2half2_rn(gz, dx);
        *(__half2*)(row + 4) = __floats2half2_rn(dy, dz);

        const float4* fp = (const float4*)(g_newfeat + (size_t)fj * HH);
        #pragma unroll
        for (int qq = 0; qq < 16; qq++) {
            float4 v = fp[qq];
            *(__half2*)(row + 6 + 4*qq)     = __floats2half2_rn(v.x, v.y);
            *(__half2*)(row + 6 + 4*qq + 2) = __floats2half2_rn(v.z, v.w);
        }
        #pragma unroll
        for (int k = 70; k < 80; k += 2)
            *(__half2*)(row + k) = __half2half2(__float2half(0.0f));
    }
    __syncthreads();

    int grp = lane >> 2;     // 0..7
    int tig = lane & 3;      // 0..3

    // running max over m-tiles; fragment position (i): d0,d1 row=grp cols 2tig,2tig+1; d2,d3 row=grp+8
    float mx[8][4];
    #pragma unroll
    for (int nt = 0; nt < 8; nt++)
        #pragma unroll
        for (int i = 0; i < 4; i++) mx[nt][i] = -3.4e38f;

    #pragma unroll
    for (int mt = 0; mt < 4; mt++) {
        float acc[8][4];
        #pragma unroll
        for (int nt = 0; nt < 8; nt++)
            #pragma unroll
            for (int i = 0; i < 4; i++) acc[nt][i] = 0.0f;

        #pragma unroll
        for (int kt = 0; kt < 5; kt++) {
            int row = mt * 16 + grp;
            int kb  = kt * 16 + 2 * tig;
            uint32_t a0 = *(const uint32_t*)(As + row * S2H_STRIDE + kb);
            uint32_t a1 = *(const uint32_t*)(As + (row + 8) * S2H_STRIDE + kb);
            uint32_t a2 = *(const uint32_t*)(As + row * S2H_STRIDE + kb + 8);
            uint32_t a3 = *(const uint32_t*)(As + (row + 8) * S2H_STRIDE + kb + 8);
            #pragma unroll
            for (int nt = 0; nt < 8; nt++) {
                int n = nt * 8 + grp;
                uint32_t b0 = *(const uint32_t*)(Bs + n * S2H_STRIDE + kb);
                uint32_t b1 = *(const uint32_t*)(Bs + n * S2H_STRIDE + kb + 8);
                mma16816(acc[nt], a0, a1, a2, a3, b0, b1);
            }
        }
        #pragma unroll
        for (int nt = 0; nt < 8; nt++)
            #pragma unroll
            for (int i = 0; i < 4; i++) mx[nt][i] = fmaxf(mx[nt][i], acc[nt][i]);
    }

    // fold rows within fragment, then reduce across grp lanes (bits 2..4)
    float m0[8], m1[8];
    #pragma unroll
    for (int nt = 0; nt < 8; nt++) {
        m0[nt] = fmaxf(mx[nt][0], mx[nt][2]);
        m1[nt] = fmaxf(mx[nt][1], mx[nt][3]);
    }
    #pragma unroll
    for (int nt = 0; nt < 8; nt++) {
        #pragma unroll
        for (int s = 4; s < 32; s <<= 1) {
            m0[nt] = fmaxf(m0[nt], __shfl_xor_sync(0xffffffffu, m0[nt], s));
            m1[nt] = fmaxf(m1[nt], __shfl_xor_sync(0xffffffffu, m1[nt], s));
        }
    }
    if (grp == 0) {   // lanes 0..3: cols 2*tig, 2*tig+1 of each n-tile
        #pragma unroll
        for (int nt = 0; nt < 8; nt++) {
            int c0 = nt * 8 + 2 * tig;
            g_h2max[bs * HH + c0]     = m0[nt] + t2[c0];
            g_h2max[bs * HH + c0 + 1] = m1[nt] + t2[c0 + 1];
        }
    }
}

// ---------------- stage 3: bottleneck mlp3 + skip, write transposed ------
#define TS 16
__global__ __launch_bounds__(256) void stage3_kernel(
    const float* __restrict__ w3a, const float* __restrict__ s3a, const float* __restrict__ t3a,
    const float* __restrict__ w3b, const float* __restrict__ s3b, const float* __restrict__ t3b,
    float* __restrict__ out)
{
    __shared__ float h2s[TS * HH];
    __shared__ float h3s[TS * H3];
    int t = threadIdx.x;
    int row0 = blockIdx.x * TS;

    for (int i = t; i < TS * HH; i += 256) h2s[i] = g_h2max[row0 * HH + i];
    __syncthreads();

    {
        float sc = s3a[t], bi = t3a[t];
        float acc[TS];
        #pragma unroll
        for (int r = 0; r < TS; r++) acc[r] = bi;
        #pragma unroll 4
        for (int i = 0; i < HH; i++) {
            float wv = w3a[i * H3 + t] * sc;
            #pragma unroll
            for (int r = 0; r < TS; r++) acc[r] += h2s[r * HH + i] * wv;
        }
        #pragma unroll
        for (int r = 0; r < TS; r++) h3s[r * H3 + t] = fmaxf(acc[r], 0.0f);
    }
    __syncthreads();

    {
        int c  = t & 63;
        int rg = t >> 6;
        float sc = s3b[c], bi = t3b[c];
        float acc[4];
        #pragma unroll
        for (int rr = 0; rr < 4; rr++) acc[rr] = bi;
        #pragma unroll 4
        for (int i = 0; i < H3; i++) {
            float wv = w3b[i * HH + c] * sc;
            #pragma unroll
            for (int rr = 0; rr < 4; rr++)
                acc[rr] += h3s[(rg * 4 + rr) * H3 + i] * wv;
        }
        #pragma unroll
        for (int rr = 0; rr < 4; rr++) {
            int row = row0 + rg * 4 + rr;
            int b = row >> 10, s = row & 1023;
            float v = acc[rr] + g_newfeat[row * HH + c];
            out[OFF_OUT + ((b * HH + c) << 10) + s] = fmaxf(v, 0.0f);
        }
    }
}

// ---------------- launch ----------------
extern "C" void kernel_launch(void* const* d_in, const int* in_sizes, int n_in,
                              void* d_out, int out_size)
{
    const float* locs  = (const float*)d_in[0];
    const float* feats = (const float*)d_in[1];
    const float* boxes = (const float*)d_in[2];
    const int*   fps   = (const int*)d_in[3];
    const int*   nbr   = (const int*)d_in[4];
    const int*   nbr2  = (const int*)d_in[5];
    const float* w1a = (const float*)d_in[6];
    const float* s1a = (const float*)d_in[7];
    const float* t1a = (const float*)d_in[8];
    const float* w1b = (const float*)d_in[9];
    const float* s1b = (const float*)d_in[10];
    const float* t1b = (const float*)d_in[11];
    const float* w2  = (const float*)d_in[12];
    const float* s2  = (const float*)d_in[13];
    const float* t2  = (const float*)d_in[14];
    const float* w3a = (const float*)d_in[15];
    const float* s3a = (const float*)d_in[16];
    const float* t3a = (const float*)d_in[17];
    const float* w3b = (const float*)d_in[18];
    const float* s3b = (const float*)d_in[19];
    const float* t3b = (const float*)d_in[20];
    float* out = (float*)d_out;

    cudaFuncSetAttribute(stage1_kernel, cudaFuncAttributeMaxDynamicSharedMemorySize, S1_SMEM);
    cudaFuncSetAttribute(stage2_mma_kernel, cudaFuncAttributeMaxDynamicSharedMemorySize, S2H_SMEM);

    prep_kernel<<<(BB * NN + 255) / 256, 256>>>(feats, boxes);
    fps_kernel<<<(BB * SS + 255) / 256, 256>>>(locs, boxes, fps, out);
    stage1_kernel<<<BB * SS / QPB, 64*QPB, S1_SMEM>>>(locs, nbr, w1a, s1a, t1a, w1b, s1b, t1b);
    stage2_mma_kernel<<<BB * SS / 8, 256, S2H_SMEM>>>(nbr2, w2, s2, t2);
    stage3_kernel<<<(BB * SS) / TS, 256>>>(w3a, s3a, t3a, w3b, s3b, t3b, out);
}

// round 15
// speedup vs baseline: 1.7957x; 1.3285x over previous
#include <cuda_runtime.h>
#include <cuda_bf16.h>
#include <cuda_fp16.h>
#include <cstdint>

// ---------------- problem constants ----------------
#define BB 8
#define NN 131072
#define SS 1024
#define KK 64
#define CC 32
#define HH 64          // 2*C
#define D1 38          // C + 6
#define D2 70          // H + 6
#define H3 256         // 4*H

// output layout (flattened concat of the 4 returned tensors)
#define OFF_LOCS  0
#define OFF_OUT   (BB*SS*3)                  // 24576
#define OFF_BOXES (OFF_OUT + BB*HH*SS)       // 548864
#define OFF_INDS  (OFF_BOXES + BB*SS*6)      // 598016

// ---------------- scratch (device globals; no allocation allowed) ----------
__device__ __half g_feats_h [BB * NN * CC];  // [B,N,C] transposed feats, fp16
__device__ float  g_dimbox  [BB * NN * 3];
__device__ float  g_fps_locs[BB * SS * 3];
__device__ float  g_fps_dim [BB * SS * 3];
__device__ float  g_newfeat [BB * SS * HH];  // stage1 out (fp32, for stage3 skip)
__device__ __half g_newfeat_h[BB * SS * HH]; // stage1 out (fp16, for stage2 gather)
__device__ float  g_h2max   [BB * SS * HH];  // stage2 output

// ---------------- mma.sync m16n8k16 fp16->fp32 ----------------
__device__ __forceinline__ void mma16816(
    float* d, uint32_t a0, uint32_t a1, uint32_t a2, uint32_t a3,
    uint32_t b0, uint32_t b1)
{
    asm volatile(
        "mma.sync.aligned.m16n8k16.row.col.f32.f16.f16.f32 "
        "{%0,%1,%2,%3}, {%4,%5,%6,%7}, {%8,%9}, {%0,%1,%2,%3};"
        : "+f"(d[0]), "+f"(d[1]), "+f"(d[2]), "+f"(d[3])
        : "r"(a0), "r"(a1), "r"(a2), "r"(a3), "r"(b0), "r"(b1));
}

// ---------------- prep: transpose feats -> fp16, compute dim boxes --------
__global__ __launch_bounds__(256) void prep_kernel(
    const float* __restrict__ feats, const float* __restrict__ boxes)
{
    int idx = blockIdx.x * blockDim.x + threadIdx.x;   // over B*N
    if (idx >= BB * NN) return;
    int b = idx >> 17;
    int n = idx & (NN - 1);

    float tmp[CC];
    #pragma unroll
    for (int c = 0; c < CC; c++)
        tmp[c] = feats[(b * CC + c) * NN + n];

    uint32_t u[16];
    #pragma unroll
    for (int p = 0; p < 16; p++) {
        __half2 h = __floats2half2_rn(tmp[2*p], tmp[2*p+1]);
        u[p] = *(uint32_t*)&h;
    }
    uint4* dst = (uint4*)(g_feats_h + ((size_t)idx << 5));
    #pragma unroll
    for (int q = 0; q < 4; q++)
        dst[q] = make_uint4(u[4*q], u[4*q+1], u[4*q+2], u[4*q+3]);

    const float* bx = boxes + (size_t)idx * 6;
    float* dd = g_dimbox + (size_t)idx * 3;
    dd[0] = bx[3] - bx[0];
    dd[1] = bx[4] - bx[1];
    dd[2] = bx[5] - bx[2];
}

// ---------------- fps gather ----------
__global__ __launch_bounds__(256) void fps_kernel(
    const float* __restrict__ locs, const float* __restrict__ boxes,
    const int* __restrict__ fps_inds, float* __restrict__ out)
{
    int idx = blockIdx.x * blockDim.x + threadIdx.x;   // over B*S
    if (idx >= BB * SS) return;
    int b = idx >> 10;
    int j = fps_inds[idx];

    const float* lp = locs + ((size_t)b * NN + j) * 3;
    float l0 = lp[0], l1 = lp[1], l2 = lp[2];
    g_fps_locs[idx*3+0] = l0; g_fps_locs[idx*3+1] = l1; g_fps_locs[idx*3+2] = l2;
    out[OFF_LOCS + idx*3 + 0] = l0;
    out[OFF_LOCS + idx*3 + 1] = l1;
    out[OFF_LOCS + idx*3 + 2] = l2;

    const float* bx = boxes + ((size_t)b * NN + j) * 6;
    float b0 = bx[0], b1 = bx[1], b2 = bx[2], b3 = bx[3], b4 = bx[4], b5 = bx[5];
    g_fps_dim[idx*3+0] = b3 - b0;
    g_fps_dim[idx*3+1] = b4 - b1;
    g_fps_dim[idx*3+2] = b5 - b2;
    out[OFF_BOXES + idx*6 + 0] = b0;
    out[OFF_BOXES + idx*6 + 1] = b1;
    out[OFF_BOXES + idx*6 + 2] = b2;
    out[OFF_BOXES + idx*6 + 3] = b3;
    out[OFF_BOXES + idx*6 + 4] = b4;
    out[OFF_BOXES + idx*6 + 5] = b5;

    out[OFF_INDS + idx] = (float)j;
}

// ================= stage 1: warp-HMMA, 1 warp = 1 query ==================
// GEMM1: A1[64 x 48pad] @ W1a[32 x 48]^T -> bias+relu -> fp16 As2 (overlays A1)
// GEMM2: As2[64 x 32] @ W1b[64 x 32]^T -> max over 64 nbrs -> bias+relu
// smem halves: Bs1 [32][56] | Bs2 [64][40] | per-warp A1 [64][56]
#define S1H_STRA 56
#define S1H_STR2 40
#define S1H_ATILE (64 * S1H_STRA)                 // 3584 halves
#define S1H_BASE  (32*S1H_STRA + 64*S1H_STR2)     // 4352 halves
#define S1H_SMEM  ((S1H_BASE + 8*S1H_ATILE) * 2)  // 66048 bytes

__global__ __launch_bounds__(256, 3) void stage1_mma_kernel(
    const float* __restrict__ locs, const int* __restrict__ nbr,
    const float* __restrict__ w1a, const float* __restrict__ s1a, const float* __restrict__ t1a,
    const float* __restrict__ w1b, const float* __restrict__ s1b, const float* __restrict__ t1b)
{
    extern __shared__ __half hs1[];
    __half* Bs1 = hs1;                       // [c=32][k<48] stride 56
    __half* Bs2 = hs1 + 32*S1H_STRA;         // [c=64][k<32] stride 40
    __shared__ float ba[CC], bb[HH];
    int tid  = threadIdx.x;
    int warp = tid >> 5;
    int lane = tid & 31;
    __half* A1 = hs1 + S1H_BASE + warp * S1H_ATILE;   // [nbr=64][k<48] stride 56

    int bs = blockIdx.x * 8 + warp;
    int b  = bs >> 10;

    // stage folded weights
    for (int idx = tid; idx < 32 * 48; idx += 256) {
        int c = idx / 48, k = idx % 48;
        float v = (k < D1) ? w1a[k * CC + c] * s1a[c] : 0.0f;
        Bs1[c * S1H_STRA + k] = __float2half(v);
    }
    for (int idx = tid; idx < 64 * 32; idx += 256) {
        int c = idx >> 5, k = idx & 31;
        Bs2[c * S1H_STR2 + k] = __float2half(w1b[k * HH + c] * s1b[c]);
    }
    if (tid < CC) ba[tid] = t1a[tid];
    if (tid < HH) bb[tid] = t1b[tid];

    // stage A1: lane handles neighbors lane, lane+32
    #pragma unroll
    for (int rr = 0; rr < 2; rr++) {
        int nb = lane + rr * 32;
        int j  = nbr[bs * KK + nb];
        __half* row = A1 + nb * S1H_STRA;

        const float* lp = locs + ((size_t)b * NN + j) * 3;
        float gx = (lp[0] - g_fps_locs[bs*3+0]) * 2.5f;
        float gy = (lp[1] - g_fps_locs[bs*3+1]) * 2.5f;
        float gz = (lp[2] - g_fps_locs[bs*3+2]) * 2.5f;
        const float* dp = g_dimbox + ((size_t)b * NN + j) * 3;
        float dx = fabsf(dp[0] - g_fps_dim[bs*3+0]);
        float dy = fabsf(dp[1] - g_fps_dim[bs*3+1]);
        float dz = fabsf(dp[2] - g_fps_dim[bs*3+2]);
        *(__half2*)(row + 0) = __floats2half2_rn(gx, gy);
        *(__half2*)(row + 2) = __floats2half2_rn(gz, dx);
        *(__half2*)(row + 4) = __floats2half2_rn(dy, dz);

        const uint4* fh = (const uint4*)(g_feats_h + (((size_t)b * NN + j) << 5));
        #pragma unroll
        for (int q = 0; q < 4; q++) {
            uint4 v = fh[q];
            *(uint32_t*)(row + 6 + 8*q)     = v.x;
            *(uint32_t*)(row + 6 + 8*q + 2) = v.y;
            *(uint32_t*)(row + 6 + 8*q + 4) = v.z;
            *(uint32_t*)(row + 6 + 8*q + 6) = v.w;
        }
        #pragma unroll
        for (int k = 38; k < 48; k += 2)
            *(uint32_t*)(row + k) = 0u;
    }
    __syncthreads();

    int grp = lane >> 2;   // 0..7
    int tig = lane & 3;    // 0..3
    __half* As2 = A1;      // overlay: writes stay below future reads

    // ---- GEMM1 + fused bias/relu -> As2 fp16 ----
    #pragma unroll
    for (int mt = 0; mt < 4; mt++) {
        float acc[4][4];
        #pragma unroll
        for (int nt = 0; nt < 4; nt++)
            #pragma unroll
            for (int i = 0; i < 4; i++) acc[nt][i] = 0.0f;

        #pragma unroll
        for (int kt = 0; kt < 3; kt++) {
            int row = mt * 16 + grp;
            int kb  = kt * 16 + 2 * tig;
            uint32_t a0 = *(const uint32_t*)(A1 + row * S1H_STRA + kb);
            uint32_t a1 = *(const uint32_t*)(A1 + (row + 8) * S1H_STRA + kb);
            uint32_t a2 = *(const uint32_t*)(A1 + row * S1H_STRA + kb + 8);
            uint32_t a3 = *(const uint32_t*)(A1 + (row + 8) * S1H_STRA + kb + 8);
            #pragma unroll
            for (int nt = 0; nt < 4; nt++) {
                int n = nt * 8 + grp;
                uint32_t b0 = *(const uint32_t*)(Bs1 + n * S1H_STRA + kb);
                uint32_t b1 = *(const uint32_t*)(Bs1 + n * S1H_STRA + kb + 8);
                mma16816(acc[nt], a0, a1, a2, a3, b0, b1);
            }
        }
        __syncwarp();
        #pragma unroll
        for (int nt = 0; nt < 4; nt++) {
            int c0 = nt * 8 + 2 * tig;
            float b0 = ba[c0], b1 = ba[c0 + 1];
            int r0 = mt * 16 + grp;
            __half2 lo = __floats2half2_rn(fmaxf(acc[nt][0] + b0, 0.0f),
                                           fmaxf(acc[nt][1] + b1, 0.0f));
            __half2 hi = __floats2half2_rn(fmaxf(acc[nt][2] + b0, 0.0f),
                                           fmaxf(acc[nt][3] + b1, 0.0f));
            *(__half2*)(As2 + r0 * S1H_STR2 + c0)       = lo;
            *(__half2*)(As2 + (r0 + 8) * S1H_STR2 + c0) = hi;
        }
        __syncwarp();
    }

    // ---- GEMM2 + running max over m-tiles ----
    float mx[8][4];
    #pragma unroll
    for (int nt = 0; nt < 8; nt++)
        #pragma unroll
        for (int i = 0; i < 4; i++) mx[nt][i] = -3.4e38f;

    #pragma unroll
    for (int mt = 0; mt < 4; mt++) {
        float acc[8][4];
        #pragma unroll
        for (int nt = 0; nt < 8; nt++)
            #pragma unroll
            for (int i = 0; i < 4; i++) acc[nt][i] = 0.0f;

        #pragma unroll
        for (int kt = 0; kt < 2; kt++) {
            int row = mt * 16 + grp;
            int kb  = kt * 16 + 2 * tig;
            uint32_t a0 = *(const uint32_t*)(As2 + row * S1H_STR2 + kb);
            uint32_t a1 = *(const uint32_t*)(As2 + (row + 8) * S1H_STR2 + kb);
            uint32_t a2 = *(const uint32_t*)(As2 + row * S1H_STR2 + kb + 8);
            uint32_t a3 = *(const uint32_t*)(As2 + (row + 8) * S1H_STR2 + kb + 8);
            #pragma unroll
            for (int nt = 0; nt < 8; nt++) {
                int n = nt * 8 + grp;
                uint32_t b0 = *(const uint32_t*)(Bs2 + n * S1H_STR2 + kb);
                uint32_t b1 = *(const uint32_t*)(Bs2 + n * S1H_STR2 + kb + 8);
                mma16816(acc[nt], a0, a1, a2, a3, b0, b1);
            }
        }
        #pragma unroll
        for (int nt = 0; nt < 8; nt++)
            #pragma unroll
            for (int i = 0; i < 4; i++) mx[nt][i] = fmaxf(mx[nt][i], acc[nt][i]);
    }

    float m0[8], m1[8];
    #pragma unroll
    for (int nt = 0; nt < 8; nt++) {
        m0[nt] = fmaxf(mx[nt][0], mx[nt][2]);
        m1[nt] = fmaxf(mx[nt][1], mx[nt][3]);
    }
    #pragma unroll
    for (int nt = 0; nt < 8; nt++) {
        #pragma unroll
        for (int s = 4; s < 32; s <<= 1) {
            m0[nt] = fmaxf(m0[nt], __shfl_xor_sync(0xffffffffu, m0[nt], s));
            m1[nt] = fmaxf(m1[nt], __shfl_xor_sync(0xffffffffu, m1[nt], s));
        }
    }
    if (grp == 0) {
        #pragma unroll
        for (int nt = 0; nt < 8; nt++) {
            int c0 = nt * 8 + 2 * tig;
            float v0 = fmaxf(m0[nt] + bb[c0], 0.0f);
            float v1 = fmaxf(m1[nt] + bb[c0 + 1], 0.0f);
            g_newfeat[bs * HH + c0]     = v0;
            g_newfeat[bs * HH + c0 + 1] = v1;
            *(__half2*)(g_newfeat_h + bs * HH + c0) = __floats2half2_rn(v0, v1);
        }
    }
}

// ================= stage 2: warp-HMMA (unchanged math, fp16 gather) ======
#define S2H_STRIDE 88
#define S2H_TILE   (64 * S2H_STRIDE)
#define S2H_SMEM   ((S2H_TILE * 9) * 2)              // 101376 bytes

__global__ __launch_bounds__(256, 2) void stage2_mma_kernel(
    const int* __restrict__ nbr2,
    const float* __restrict__ w2, const float* __restrict__ s2, const float* __restrict__ t2)
{
    extern __shared__ __half hsm[];
    __half* Bs = hsm;                         // [n=64][k<80], stride 88
    int tid  = threadIdx.x;
    int warp = tid >> 5;
    int lane = tid & 31;
    __half* As = hsm + S2H_TILE * (1 + warp); // [nbr=64][k<80], stride 88

    int bs = blockIdx.x * 8 + warp;
    int b  = bs >> 10;

    for (int idx = tid; idx < 64 * 80; idx += 256) {
        int n = idx / 80, k = idx % 80;
        float v = (k < D2) ? w2[k * HH + n] * s2[n] : 0.0f;
        Bs[n * S2H_STRIDE + k] = __float2half(v);
    }

    #pragma unroll
    for (int rr = 0; rr < 2; rr++) {
        int nb = lane + rr * 32;
        int j  = nbr2[bs * KK + nb];
        int fj = (b << 10) + j;
        __half* row = As + nb * S2H_STRIDE;

        float gx = (g_fps_locs[fj*3+0] - g_fps_locs[bs*3+0]) * 1.25f;
        float gy = (g_fps_locs[fj*3+1] - g_fps_locs[bs*3+1]) * 1.25f;
        float gz = (g_fps_locs[fj*3+2] - g_fps_locs[bs*3+2]) * 1.25f;
        float dx = fabsf(g_fps_dim[fj*3+0] - g_fps_dim[bs*3+0]);
        float dy = fabsf(g_fps_dim[fj*3+1] - g_fps_dim[bs*3+1]);
        float dz = fabsf(g_fps_dim[fj*3+2] - g_fps_dim[bs*3+2]);
        *(__half2*)(row + 0) = __floats2half2_rn(gx, gy);
        *(__half2*)(row + 2) = __floats2half2_rn(gz, dx);
        *(__half2*)(row + 4) = __floats2half2_rn(dy, dz);

        const uint4* fh = (const uint4*)(g_newfeat_h + ((size_t)fj << 6));
        #pragma unroll
        for (int q = 0; q < 8; q++) {
            uint4 v = fh[q];
            *(uint32_t*)(row + 6 + 8*q)     = v.x;
            *(uint32_t*)(row + 6 + 8*q + 2) = v.y;
            *(uint32_t*)(row + 6 + 8*q + 4) = v.z;
            *(uint32_t*)(row + 6 + 8*q + 6) = v.w;
        }
        #pragma unroll
        for (int k = 70; k < 80; k += 2)
            *(uint32_t*)(row + k) = 0u;
    }
    __syncthreads();

    int grp = lane >> 2;
    int tig = lane & 3;

    float mx[8][4];
    #pragma unroll
    for (int nt = 0; nt < 8; nt++)
        #pragma unroll
        for (int i = 0; i < 4; i++) mx[nt][i] = -3.4e38f;

    #pragma unroll
    for (int mt = 0; mt < 4; mt++) {
        float acc[8][4];
        #pragma unroll
        for (int nt = 0; nt < 8; nt++)
            #pragma unroll
            for (int i = 0; i < 4; i++) acc[nt][i] = 0.0f;

        #pragma unroll
        for (int kt = 0; kt < 5; kt++) {
            int row = mt * 16 + grp;
            int kb  = kt * 16 + 2 * tig;
            uint32_t a0 = *(const uint32_t*)(As + row * S2H_STRIDE + kb);
            uint32_t a1 = *(const uint32_t*)(As + (row + 8) * S2H_STRIDE + kb);
            uint32_t a2 = *(const uint32_t*)(As + row * S2H_STRIDE + kb + 8);
            uint32_t a3 = *(const uint32_t*)(As + (row + 8) * S2H_STRIDE + kb + 8);
            #pragma unroll
            for (int nt = 0; nt < 8; nt++) {
                int n = nt * 8 + grp;
                uint32_t b0 = *(const uint32_t*)(Bs + n * S2H_STRIDE + kb);
                uint32_t b1 = *(const uint32_t*)(Bs + n * S2H_STRIDE + kb + 8);
                mma16816(acc[nt], a0, a1, a2, a3, b0, b1);
            }
        }
        #pragma unroll
        for (int nt = 0; nt < 8; nt++)
            #pragma unroll
            for (int i = 0; i < 4; i++) mx[nt][i] = fmaxf(mx[nt][i], acc[nt][i]);
    }

    float m0[8], m1[8];
    #pragma unroll
    for (int nt = 0; nt < 8; nt++) {
        m0[nt] = fmaxf(mx[nt][0], mx[nt][2]);
        m1[nt] = fmaxf(mx[nt][1], mx[nt][3]);
    }
    #pragma unroll
    for (int nt = 0; nt < 8; nt++) {
        #pragma unroll
        for (int s = 4; s < 32; s <<= 1) {
            m0[nt] = fmaxf(m0[nt], __shfl_xor_sync(0xffffffffu, m0[nt], s));
            m1[nt] = fmaxf(m1[nt], __shfl_xor_sync(0xffffffffu, m1[nt], s));
        }
    }
    if (grp == 0) {
        #pragma unroll
        for (int nt = 0; nt < 8; nt++) {
            int c0 = nt * 8 + 2 * tig;
            g_h2max[bs * HH + c0]     = m0[nt] + t2[c0];
            g_h2max[bs * HH + c0 + 1] = m1[nt] + t2[c0 + 1];
        }
    }
}

// ---------------- stage 3: bottleneck mlp3 + skip, write transposed ------
#define TS 16
__global__ __launch_bounds__(256) void stage3_kernel(
    const float* __restrict__ w3a, const float* __restrict__ s3a, const float* __restrict__ t3a,
    const float* __restrict__ w3b, const float* __restrict__ s3b, const float* __restrict__ t3b,
    float* __restrict__ out)
{
    __shared__ float h2s[TS * HH];
    __shared__ float h3s[TS * H3];
    int t = threadIdx.x;
    int row0 = blockIdx.x * TS;

    for (int i = t; i < TS * HH; i += 256) h2s[i] = g_h2max[row0 * HH + i];
    __syncthreads();

    {
        float sc = s3a[t], bi = t3a[t];
        float acc[TS];
        #pragma unroll
        for (int r = 0; r < TS; r++) acc[r] = bi;
        #pragma unroll 4
        for (int i = 0; i < HH; i++) {
            float wv = w3a[i * H3 + t] * sc;
            #pragma unroll
            for (int r = 0; r < TS; r++) acc[r] += h2s[r * HH + i] * wv;
        }
        #pragma unroll
        for (int r = 0; r < TS; r++) h3s[r * H3 + t] = fmaxf(acc[r], 0.0f);
    }
    __syncthreads();

    {
        int c  = t & 63;
        int rg = t >> 6;
        float sc = s3b[c], bi = t3b[c];
        float acc[4];
        #pragma unroll
        for (int rr = 0; rr < 4; rr++) acc[rr] = bi;
        #pragma unroll 4
        for (int i = 0; i < H3; i++) {
            float wv = w3b[i * HH + c] * sc;
            #pragma unroll
            for (int rr = 0; rr < 4; rr++)
                acc[rr] += h3s[(rg * 4 + rr) * H3 + i] * wv;
        }
        #pragma unroll
        for (int rr = 0; rr < 4; rr++) {
            int row = row0 + rg * 4 + rr;
            int b = row >> 10, s = row & 1023;
            float v = acc[rr] + g_newfeat[row * HH + c];
            out[OFF_OUT + ((b * HH + c) << 10) + s] = fmaxf(v, 0.0f);
        }
    }
}

// ---------------- launch ----------------
extern "C" void kernel_launch(void* const* d_in, const int* in_sizes, int n_in,
                              void* d_out, int out_size)
{
    const float* locs  = (const float*)d_in[0];
    const float* feats = (const float*)d_in[1];
    const float* boxes = (const float*)d_in[2];
    const int*   fps   = (const int*)d_in[3];
    const int*   nbr   = (const int*)d_in[4];
    const int*   nbr2  = (const int*)d_in[5];
    const float* w1a = (const float*)d_in[6];
    const float* s1a = (const float*)d_in[7];
    const float* t1a = (const float*)d_in[8];
    const float* w1b = (const float*)d_in[9];
    const float* s1b = (const float*)d_in[10];
    const float* t1b = (const float*)d_in[11];
    const float* w2  = (const float*)d_in[12];
    const float* s2  = (const float*)d_in[13];
    const float* t2  = (const float*)d_in[14];
    const float* w3a = (const float*)d_in[15];
    const float* s3a = (const float*)d_in[16];
    const float* t3a = (const float*)d_in[17];
    const float* w3b = (const float*)d_in[18];
    const float* s3b = (const float*)d_in[19];
    const float* t3b = (const float*)d_in[20];
    float* out = (float*)d_out;

    cudaFuncSetAttribute(stage1_mma_kernel, cudaFuncAttributeMaxDynamicSharedMemorySize, S1H_SMEM);
    cudaFuncSetAttribute(stage2_mma_kernel, cudaFuncAttributeMaxDynamicSharedMemorySize, S2H_SMEM);

    prep_kernel<<<(BB * NN + 255) / 256, 256>>>(feats, boxes);
    fps_kernel<<<(BB * SS + 255) / 256, 256>>>(locs, boxes, fps, out);
    stage1_mma_kernel<<<BB * SS / 8, 256, S1H_SMEM>>>(locs, nbr, w1a, s1a, t1a, w1b, s1b, t1b);
    stage2_mma_kernel<<<BB * SS / 8, 256, S2H_SMEM>>>(nbr2, w2, s2, t2);
    stage3_kernel<<<(BB * SS) / TS, 256>>>(w3a, s3a, t3a, w3b, s3b, t3b, out);
}

// round 16
// speedup vs baseline: 1.9186x; 1.0684x over previous
#include <cuda_runtime.h>
#include <cuda_bf16.h>
#include <cuda_fp16.h>
#include <cstdint>

// ---------------- problem constants ----------------
#define BB 8
#define NN 131072
#define SS 1024
#define KK 64
#define CC 32
#define HH 64          // 2*C
#define D1 38          // C + 6
#define D2 70          // H + 6
#define H3 256         // 4*H

// output layout (flattened concat of the 4 returned tensors)
#define OFF_LOCS  0
#define OFF_OUT   (BB*SS*3)                  // 24576
#define OFF_BOXES (OFF_OUT + BB*HH*SS)       // 548864
#define OFF_INDS  (OFF_BOXES + BB*SS*6)      // 598016

// ---------------- scratch (device globals; no allocation allowed) ----------
__device__ __half g_feats_h [BB * NN * CC];  // [B,N,C] transposed feats, fp16
__device__ float  g_dimbox  [BB * NN * 3];
__device__ float  g_fps_locs[BB * SS * 3];
__device__ float  g_fps_dim [BB * SS * 3];
__device__ float  g_newfeat [BB * SS * HH];  // stage1 out (fp32, for stage3 skip)
__device__ __half g_newfeat_h[BB * SS * HH]; // stage1 out (fp16, for stage2 gather)
__device__ float  g_h2max   [BB * SS * HH];  // stage2 output

// ---------------- helpers ----------------
__device__ __forceinline__ uint32_t smem_u32(const void* p) {
    uint32_t a;
    asm("{ .reg .u64 t; cvta.to.shared.u64 t, %1; cvt.u32.u64 %0, t; }" : "=r"(a) : "l"(p));
    return a;
}
__device__ __forceinline__ void cp_async16(uint32_t dst, const void* src) {
    asm volatile("cp.async.ca.shared.global [%0], [%1], 16;"
                 :: "r"(dst), "l"(__cvta_generic_to_global(src)) : "memory");
}
__device__ __forceinline__ void cp_async_wait_all() {
    asm volatile("cp.async.commit_group;" ::: "memory");
    asm volatile("cp.async.wait_group 0;" ::: "memory");
}

__device__ __forceinline__ void mma16816(
    float* d, uint32_t a0, uint32_t a1, uint32_t a2, uint32_t a3,
    uint32_t b0, uint32_t b1)
{
    asm volatile(
        "mma.sync.aligned.m16n8k16.row.col.f32.f16.f16.f32 "
        "{%0,%1,%2,%3}, {%4,%5,%6,%7}, {%8,%9}, {%0,%1,%2,%3};"
        : "+f"(d[0]), "+f"(d[1]), "+f"(d[2]), "+f"(d[3])
        : "r"(a0), "r"(a1), "r"(a2), "r"(a3), "r"(b0), "r"(b1));
}

// ---------------- prep: transpose feats -> fp16, compute dim boxes --------
__global__ __launch_bounds__(256) void prep_kernel(
    const float* __restrict__ feats, const float* __restrict__ boxes)
{
    int idx = blockIdx.x * blockDim.x + threadIdx.x;   // over B*N
    if (idx >= BB * NN) return;
    int b = idx >> 17;
    int n = idx & (NN - 1);

    float tmp[CC];
    #pragma unroll
    for (int c = 0; c < CC; c++)
        tmp[c] = feats[(b * CC + c) * NN + n];

    uint32_t u[16];
    #pragma unroll
    for (int p = 0; p < 16; p++) {
        __half2 h = __floats2half2_rn(tmp[2*p], tmp[2*p+1]);
        u[p] = *(uint32_t*)&h;
    }
    uint4* dst = (uint4*)(g_feats_h + ((size_t)idx << 5));
    #pragma unroll
    for (int q = 0; q < 4; q++)
        dst[q] = make_uint4(u[4*q], u[4*q+1], u[4*q+2], u[4*q+3]);

    const float* bx = boxes + (size_t)idx * 6;
    float* dd = g_dimbox + (size_t)idx * 3;
    dd[0] = bx[3] - bx[0];
    dd[1] = bx[4] - bx[1];
    dd[2] = bx[5] - bx[2];
}

// ---------------- fps gather ----------
__global__ __launch_bounds__(256) void fps_kernel(
    const float* __restrict__ locs, const float* __restrict__ boxes,
    const int* __restrict__ fps_inds, float* __restrict__ out)
{
    int idx = blockIdx.x * blockDim.x + threadIdx.x;   // over B*S
    if (idx >= BB * SS) return;
    int b = idx >> 10;
    int j = fps_inds[idx];

    const float* lp = locs + ((size_t)b * NN + j) * 3;
    float l0 = lp[0], l1 = lp[1], l2 = lp[2];
    g_fps_locs[idx*3+0] = l0; g_fps_locs[idx*3+1] = l1; g_fps_locs[idx*3+2] = l2;
    out[OFF_LOCS + idx*3 + 0] = l0;
    out[OFF_LOCS + idx*3 + 1] = l1;
    out[OFF_LOCS + idx*3 + 2] = l2;

    const float* bx = boxes + ((size_t)b * NN + j) * 6;
    float b0 = bx[0], b1 = bx[1], b2 = bx[2], b3 = bx[3], b4 = bx[4], b5 = bx[5];
    g_fps_dim[idx*3+0] = b3 - b0;
    g_fps_dim[idx*3+1] = b4 - b1;
    g_fps_dim[idx*3+2] = b5 - b2;
    out[OFF_BOXES + idx*6 + 0] = b0;
    out[OFF_BOXES + idx*6 + 1] = b1;
    out[OFF_BOXES + idx*6 + 2] = b2;
    out[OFF_BOXES + idx*6 + 3] = b3;
    out[OFF_BOXES + idx*6 + 4] = b4;
    out[OFF_BOXES + idx*6 + 5] = b5;

    out[OFF_INDS + idx] = (float)j;
}

// ================= stage 1: warp-HMMA, 1 warp = 1 query ==================
// K-order: k=0..31 feats, k=32..37 geo, k=38..47 pad (B rows reordered identically)
// GEMM1: A1[64 x 48] @ W1a[32 x 48]^T -> bias+relu -> fp16 As2 (overlays A1)
// GEMM2: As2[64 x 32] @ W1b[64 x 32]^T -> max over 64 nbrs -> bias+relu
#define S1H_STRA 56
#define S1H_STR2 40
#define S1H_ATILE (64 * S1H_STRA)                 // 3584 halves
#define S1H_BASE  (32*S1H_STRA + 64*S1H_STR2)     // 4352 halves
#define S1H_SMEM  ((S1H_BASE + 8*S1H_ATILE) * 2)  // 66048 bytes

__global__ __launch_bounds__(256, 3) void stage1_mma_kernel(
    const float* __restrict__ locs, const int* __restrict__ nbr,
    const float* __restrict__ w1a, const float* __restrict__ s1a, const float* __restrict__ t1a,
    const float* __restrict__ w1b, const float* __restrict__ s1b, const float* __restrict__ t1b)
{
    extern __shared__ __half hs1[];
    __half* Bs1 = hs1;                       // [c=32][k<48] stride 56
    __half* Bs2 = hs1 + 32*S1H_STRA;         // [c=64][k<32] stride 40
    __shared__ float ba[CC], bb[HH];
    int tid  = threadIdx.x;
    int warp = tid >> 5;
    int lane = tid & 31;
    __half* A1 = hs1 + S1H_BASE + warp * S1H_ATILE;   // [nbr=64][k<48] stride 56

    int bs = blockIdx.x * 8 + warp;
    int b  = bs >> 10;

    // stage A1: feats via cp.async (k=0..31), geo computed (k=32..37), pad 38..47
    #pragma unroll
    for (int rr = 0; rr < 2; rr++) {
        int nb = lane + rr * 32;
        int j  = nbr[bs * KK + nb];
        __half* row = A1 + nb * S1H_STRA;
        uint32_t rsm = smem_u32(row);
        const __half* src = g_feats_h + (((size_t)b * NN + j) << 5);
        #pragma unroll
        for (int q = 0; q < 4; q++) cp_async16(rsm + 16*q, src + 8*q);

        const float* lp = locs + ((size_t)b * NN + j) * 3;
        float gx = (lp[0] - g_fps_locs[bs*3+0]) * 2.5f;
        float gy = (lp[1] - g_fps_locs[bs*3+1]) * 2.5f;
        float gz = (lp[2] - g_fps_locs[bs*3+2]) * 2.5f;
        const float* dp = g_dimbox + ((size_t)b * NN + j) * 3;
        float dx = fabsf(dp[0] - g_fps_dim[bs*3+0]);
        float dy = fabsf(dp[1] - g_fps_dim[bs*3+1]);
        float dz = fabsf(dp[2] - g_fps_dim[bs*3+2]);
        *(__half2*)(row + 32) = __floats2half2_rn(gx, gy);
        *(__half2*)(row + 34) = __floats2half2_rn(gz, dx);
        *(__half2*)(row + 36) = __floats2half2_rn(dy, dz);
        #pragma unroll
        for (int k = 38; k < 48; k += 2)
            *(uint32_t*)(row + k) = 0u;
    }

    // stage folded weights (same K-order)
    for (int idx = tid; idx < 32 * 48; idx += 256) {
        int c = idx / 48, k = idx % 48;
        float v;
        if (k < 32)      v = w1a[(6 + k) * CC + c] * s1a[c];
        else if (k < 38) v = w1a[(k - 32) * CC + c] * s1a[c];
        else             v = 0.0f;
        Bs1[c * S1H_STRA + k] = __float2half(v);
    }
    for (int idx = tid; idx < 64 * 32; idx += 256) {
        int c = idx >> 5, k = idx & 31;
        Bs2[c * S1H_STR2 + k] = __float2half(w1b[k * HH + c] * s1b[c]);
    }
    if (tid < CC) ba[tid] = t1a[tid];
    if (tid < HH) bb[tid] = t1b[tid];

    cp_async_wait_all();
    __syncthreads();

    int grp = lane >> 2;   // 0..7
    int tig = lane & 3;    // 0..3
    __half* As2 = A1;      // overlay: writes stay below future reads

    // ---- GEMM1 + fused bias/relu -> As2 fp16 ----
    #pragma unroll
    for (int mt = 0; mt < 4; mt++) {
        float acc[4][4];
        #pragma unroll
        for (int nt = 0; nt < 4; nt++)
            #pragma unroll
            for (int i = 0; i < 4; i++) acc[nt][i] = 0.0f;

        #pragma unroll
        for (int kt = 0; kt < 3; kt++) {
            int row = mt * 16 + grp;
            int kb  = kt * 16 + 2 * tig;
            uint32_t a0 = *(const uint32_t*)(A1 + row * S1H_STRA + kb);
            uint32_t a1 = *(const uint32_t*)(A1 + (row + 8) * S1H_STRA + kb);
            uint32_t a2 = *(const uint32_t*)(A1 + row * S1H_STRA + kb + 8);
            uint32_t a3 = *(const uint32_t*)(A1 + (row + 8) * S1H_STRA + kb + 8);
            #pragma unroll
            for (int nt = 0; nt < 4; nt++) {
                int n = nt * 8 + grp;
                uint32_t b0 = *(const uint32_t*)(Bs1 + n * S1H_STRA + kb);
                uint32_t b1 = *(const uint32_t*)(Bs1 + n * S1H_STRA + kb + 8);
                mma16816(acc[nt], a0, a1, a2, a3, b0, b1);
            }
        }
        __syncwarp();
        #pragma unroll
        for (int nt = 0; nt < 4; nt++) {
            int c0 = nt * 8 + 2 * tig;
            float b0 = ba[c0], b1 = ba[c0 + 1];
            int r0 = mt * 16 + grp;
            __half2 lo = __floats2half2_rn(fmaxf(acc[nt][0] + b0, 0.0f),
                                           fmaxf(acc[nt][1] + b1, 0.0f));
            __half2 hi = __floats2half2_rn(fmaxf(acc[nt][2] + b0, 0.0f),
                                           fmaxf(acc[nt][3] + b1, 0.0f));
            *(__half2*)(As2 + r0 * S1H_STR2 + c0)       = lo;
            *(__half2*)(As2 + (r0 + 8) * S1H_STR2 + c0) = hi;
        }
        __syncwarp();
    }

    // ---- GEMM2 + running max over m-tiles ----
    float mx[8][4];
    #pragma unroll
    for (int nt = 0; nt < 8; nt++)
        #pragma unroll
        for (int i = 0; i < 4; i++) mx[nt][i] = -3.4e38f;

    #pragma unroll
    for (int mt = 0; mt < 4; mt++) {
        float acc[8][4];
        #pragma unroll
        for (int nt = 0; nt < 8; nt++)
            #pragma unroll
            for (int i = 0; i < 4; i++) acc[nt][i] = 0.0f;

        #pragma unroll
        for (int kt = 0; kt < 2; kt++) {
            int row = mt * 16 + grp;
            int kb  = kt * 16 + 2 * tig;
            uint32_t a0 = *(const uint32_t*)(As2 + row * S1H_STR2 + kb);
            uint32_t a1 = *(const uint32_t*)(As2 + (row + 8) * S1H_STR2 + kb);
            uint32_t a2 = *(const uint32_t*)(As2 + row * S1H_STR2 + kb + 8);
            uint32_t a3 = *(const uint32_t*)(As2 + (row + 8) * S1H_STR2 + kb + 8);
            #pragma unroll
            for (int nt = 0; nt < 8; nt++) {
                int n = nt * 8 + grp;
                uint32_t b0 = *(const uint32_t*)(Bs2 + n * S1H_STR2 + kb);
                uint32_t b1 = *(const uint32_t*)(Bs2 + n * S1H_STR2 + kb + 8);
                mma16816(acc[nt], a0, a1, a2, a3, b0, b1);
            }
        }
        #pragma unroll
        for (int nt = 0; nt < 8; nt++)
            #pragma unroll
            for (int i = 0; i < 4; i++) mx[nt][i] = fmaxf(mx[nt][i], acc[nt][i]);
    }

    float m0[8], m1[8];
    #pragma unroll
    for (int nt = 0; nt < 8; nt++) {
        m0[nt] = fmaxf(mx[nt][0], mx[nt][2]);
        m1[nt] = fmaxf(mx[nt][1], mx[nt][3]);
    }
    #pragma unroll
    for (int nt = 0; nt < 8; nt++) {
        #pragma unroll
        for (int s = 4; s < 32; s <<= 1) {
            m0[nt] = fmaxf(m0[nt], __shfl_xor_sync(0xffffffffu, m0[nt], s));
            m1[nt] = fmaxf(m1[nt], __shfl_xor_sync(0xffffffffu, m1[nt], s));
        }
    }
    if (grp == 0) {
        #pragma unroll
        for (int nt = 0; nt < 8; nt++) {
            int c0 = nt * 8 + 2 * tig;
            float v0 = fmaxf(m0[nt] + bb[c0], 0.0f);
            float v1 = fmaxf(m1[nt] + bb[c0 + 1], 0.0f);
            g_newfeat[bs * HH + c0]     = v0;
            g_newfeat[bs * HH + c0 + 1] = v1;
            *(__half2*)(g_newfeat_h + bs * HH + c0) = __floats2half2_rn(v0, v1);
        }
    }
}

// ================= stage 2: warp-HMMA, cp.async staging ==================
// K-order: k=0..63 feats, k=64..69 geo, k=70..79 pad
#define S2H_STRIDE 88
#define S2H_TILE   (64 * S2H_STRIDE)
#define S2H_SMEM   ((S2H_TILE * 9) * 2)              // 101376 bytes

__global__ __launch_bounds__(256, 2) void stage2_mma_kernel(
    const int* __restrict__ nbr2,
    const float* __restrict__ w2, const float* __restrict__ s2, const float* __restrict__ t2)
{
    extern __shared__ __half hsm[];
    __half* Bs = hsm;                         // [n=64][k<80], stride 88
    int tid  = threadIdx.x;
    int warp = tid >> 5;
    int lane = tid & 31;
    __half* As = hsm + S2H_TILE * (1 + warp); // [nbr=64][k<80], stride 88

    int bs = blockIdx.x * 8 + warp;
    int b  = bs >> 10;

    // stage A: feats via cp.async (k=0..63), geo (k=64..69), pad 70..79
    #pragma unroll
    for (int rr = 0; rr < 2; rr++) {
        int nb = lane + rr * 32;
        int j  = nbr2[bs * KK + nb];
        int fj = (b << 10) + j;
        __half* row = As + nb * S2H_STRIDE;
        uint32_t rsm = smem_u32(row);
        const __half* src = g_newfeat_h + ((size_t)fj << 6);
        #pragma unroll
        for (int q = 0; q < 8; q++) cp_async16(rsm + 16*q, src + 8*q);

        float gx = (g_fps_locs[fj*3+0] - g_fps_locs[bs*3+0]) * 1.25f;
        float gy = (g_fps_locs[fj*3+1] - g_fps_locs[bs*3+1]) * 1.25f;
        float gz = (g_fps_locs[fj*3+2] - g_fps_locs[bs*3+2]) * 1.25f;
        float dx = fabsf(g_fps_dim[fj*3+0] - g_fps_dim[bs*3+0]);
        float dy = fabsf(g_fps_dim[fj*3+1] - g_fps_dim[bs*3+1]);
        float dz = fabsf(g_fps_dim[fj*3+2] - g_fps_dim[bs*3+2]);
        *(__half2*)(row + 64) = __floats2half2_rn(gx, gy);
        *(__half2*)(row + 66) = __floats2half2_rn(gz, dx);
        *(__half2*)(row + 68) = __floats2half2_rn(dy, dz);
        #pragma unroll
        for (int k = 70; k < 80; k += 2)
            *(uint32_t*)(row + k) = 0u;
    }

    // stage B (same K-order)
    for (int idx = tid; idx < 64 * 80; idx += 256) {
        int n = idx / 80, k = idx % 80;
        float v;
        if (k < 64)      v = w2[(6 + k) * HH + n] * s2[n];
        else if (k < 70) v = w2[(k - 64) * HH + n] * s2[n];
        else             v = 0.0f;
        Bs[n * S2H_STRIDE + k] = __float2half(v);
    }

    cp_async_wait_all();
    __syncthreads();

    int grp = lane >> 2;
    int tig = lane & 3;

    float mx[8][4];
    #pragma unroll
    for (int nt = 0; nt < 8; nt++)
        #pragma unroll
        for (int i = 0; i < 4; i++) mx[nt][i] = -3.4e38f;

    #pragma unroll
    for (int mt = 0; mt < 4; mt++) {
        float acc[8][4];
        #pragma unroll
        for (int nt = 0; nt < 8; nt++)
            #pragma unroll
            for (int i = 0; i < 4; i++) acc[nt][i] = 0.0f;

        #pragma unroll
        for (int kt = 0; kt < 5; kt++) {
            int row = mt * 16 + grp;
            int kb  = kt * 16 + 2 * tig;
            uint32_t a0 = *(const uint32_t*)(As + row * S2H_STRIDE + kb);
            uint32_t a1 = *(const uint32_t*)(As + (row + 8) * S2H_STRIDE + kb);
            uint32_t a2 = *(const uint32_t*)(As + row * S2H_STRIDE + kb + 8);
            uint32_t a3 = *(const uint32_t*)(As + (row + 8) * S2H_STRIDE + kb + 8);
            #pragma unroll
            for (int nt = 0; nt < 8; nt++) {
                int n = nt * 8 + grp;
                uint32_t b0 = *(const uint32_t*)(Bs + n * S2H_STRIDE + kb);
                uint32_t b1 = *(const uint32_t*)(Bs + n * S2H_STRIDE + kb + 8);
                mma16816(acc[nt], a0, a1, a2, a3, b0, b1);
            }
        }
        #pragma unroll
        for (int nt = 0; nt < 8; nt++)
            #pragma unroll
            for (int i = 0; i < 4; i++) mx[nt][i] = fmaxf(mx[nt][i], acc[nt][i]);
    }

    float m0[8], m1[8];
    #pragma unroll
    for (int nt = 0; nt < 8; nt++) {
        m0[nt] = fmaxf(mx[nt][0], mx[nt][2]);
        m1[nt] = fmaxf(mx[nt][1], mx[nt][3]);
    }
    #pragma unroll
    for (int nt = 0; nt < 8; nt++) {
        #pragma unroll
        for (int s = 4; s < 32; s <<= 1) {
            m0[nt] = fmaxf(m0[nt], __shfl_xor_sync(0xffffffffu, m0[nt], s));
            m1[nt] = fmaxf(m1[nt], __shfl_xor_sync(0xffffffffu, m1[nt], s));
        }
    }
    if (grp == 0) {
        #pragma unroll
        for (int nt = 0; nt < 8; nt++) {
            int c0 = nt * 8 + 2 * tig;
            g_h2max[bs * HH + c0]     = m0[nt] + t2[c0];
            g_h2max[bs * HH + c0 + 1] = m1[nt] + t2[c0 + 1];
        }
    }
}

// ---------------- stage 3: bottleneck mlp3 + skip, write transposed ------
#define TS 16
__global__ __launch_bounds__(256) void stage3_kernel(
    const float* __restrict__ w3a, const float* __restrict__ s3a, const float* __restrict__ t3a,
    const float* __restrict__ w3b, const float* __restrict__ s3b, const float* __restrict__ t3b,
    float* __restrict__ out)
{
    __shared__ float h2s[TS * HH];
    __shared__ float h3s[TS * H3];
    int t = threadIdx.x;
    int row0 = blockIdx.x * TS;

    for (int i = t; i < TS * HH; i += 256) h2s[i] = g_h2max[row0 * HH + i];
    __syncthreads();

    {
        float sc = s3a[t], bi = t3a[t];
        float acc[TS];
        #pragma unroll
        for (int r = 0; r < TS; r++) acc[r] = bi;
        #pragma unroll 4
        for (int i = 0; i < HH; i++) {
            float wv = w3a[i * H3 + t] * sc;
            #pragma unroll
            for (int r = 0; r < TS; r++) acc[r] += h2s[r * HH + i] * wv;
        }
        #pragma unroll
        for (int r = 0; r < TS; r++) h3s[r * H3 + t] = fmaxf(acc[r], 0.0f);
    }
    __syncthreads();

    {
        int c  = t & 63;
        int rg = t >> 6;
        float sc = s3b[c], bi = t3b[c];
        float acc[4];
        #pragma unroll
        for (int rr = 0; rr < 4; rr++) acc[rr] = bi;
        #pragma unroll 4
        for (int i = 0; i < H3; i++) {
            float wv = w3b[i * HH + c] * sc;
            #pragma unroll
            for (int rr = 0; rr < 4; rr++)
                acc[rr] += h3s[(rg * 4 + rr) * H3 + i] * wv;
        }
        #pragma unroll
        for (int rr = 0; rr < 4; rr++) {
            int row = row0 + rg * 4 + rr;
            int b = row >> 10, s = row & 1023;
            float v = acc[rr] + g_newfeat[row * HH + c];
            out[OFF_OUT + ((b * HH + c) << 10) + s] = fmaxf(v, 0.0f);
        }
    }
}

// ---------------- launch ----------------
extern "C" void kernel_launch(void* const* d_in, const int* in_sizes, int n_in,
                              void* d_out, int out_size)
{
    const float* locs  = (const float*)d_in[0];
    const float* feats = (const float*)d_in[1];
    const float* boxes = (const float*)d_in[2];
    const int*   fps   = (const int*)d_in[3];
    const int*   nbr   = (const int*)d_in[4];
    const int*   nbr2  = (const int*)d_in[5];
    const float* w1a = (const float*)d_in[6];
    const float* s1a = (const float*)d_in[7];
    const float* t1a = (const float*)d_in[8];
    const float* w1b = (const float*)d_in[9];
    const float* s1b = (const float*)d_in[10];
    const float* t1b = (const float*)d_in[11];
    const float* w2  = (const float*)d_in[12];
    const float* s2  = (const float*)d_in[13];
    const float* t2  = (const float*)d_in[14];
    const float* w3a = (const float*)d_in[15];
    const float* s3a = (const float*)d_in[16];
    const float* t3a = (const float*)d_in[17];
    const float* w3b = (const float*)d_in[18];
    const float* s3b = (const float*)d_in[19];
    const float* t3b = (const float*)d_in[20];
    float* out = (float*)d_out;

    cudaFuncSetAttribute(stage1_mma_kernel, cudaFuncAttributeMaxDynamicSharedMemorySize, S1H_SMEM);
    cudaFuncSetAttribute(stage2_mma_kernel, cudaFuncAttributeMaxDynamicSharedMemorySize, S2H_SMEM);

    prep_kernel<<<(BB * NN + 255) / 256, 256>>>(feats, boxes);
    fps_kernel<<<(BB * SS + 255) / 256, 256>>>(locs, boxes, fps, out);
    stage1_mma_kernel<<<BB * SS / 8, 256, S1H_SMEM>>>(locs, nbr, w1a, s1a, t1a, w1b, s1b, t1b);
    stage2_mma_kernel<<<BB * SS / 8, 256, S2H_SMEM>>>(nbr2, w2, s2, t2);
    stage3_kernel<<<(BB * SS) / TS, 256>>>(w3a, s3a, t3a, w3b, s3b, t3b, out);
}

// round 17
// speedup vs baseline: 1.9750x; 1.0294x over previous
#include <cuda_runtime.h>
#include <cuda_bf16.h>
#include <cuda_fp16.h>
#include <cstdint>

// ---------------- problem constants ----------------
#define BB 8
#define NN 131072
#define SS 1024
#define KK 64
#define CC 32
#define HH 64          // 2*C
#define D1 38          // C + 6
#define D2 70          // H + 6
#define H3 256         // 4*H

// output layout (flattened concat of the 4 returned tensors)
#define OFF_LOCS  0
#define OFF_OUT   (BB*SS*3)                  // 24576
#define OFF_BOXES (OFF_OUT + BB*HH*SS)       // 548864
#define OFF_INDS  (OFF_BOXES + BB*SS*6)      // 598016

// ---------------- scratch (device globals; no allocation allowed) ----------
__device__ __half g_feats_h [BB * NN * CC];  // [B,N,C] transposed feats, fp16
__device__ float  g_dimbox  [BB * NN * 3];
__device__ float  g_fps_locs[BB * SS * 3];
__device__ float  g_fps_dim [BB * SS * 3];
__device__ float  g_newfeat [BB * SS * HH];  // stage1 out (fp32, for stage3 skip)
__device__ __half g_newfeat_h[BB * SS * HH]; // stage1 out (fp16, for stage2 gather)
__device__ float  g_h2max   [BB * SS * HH];  // stage2 output

// ---------------- helpers ----------------
__device__ __forceinline__ uint32_t smem_u32(const void* p) {
    uint32_t a;
    asm("{ .reg .u64 t; cvta.to.shared.u64 t, %1; cvt.u32.u64 %0, t; }" : "=r"(a) : "l"(p));
    return a;
}
__device__ __forceinline__ void cp_async16(uint32_t dst, const void* src) {
    asm volatile("cp.async.ca.shared.global [%0], [%1], 16;"
                 :: "r"(dst), "l"(__cvta_generic_to_global(src)) : "memory");
}
__device__ __forceinline__ void cp_async_wait_all() {
    asm volatile("cp.async.commit_group;" ::: "memory");
    asm volatile("cp.async.wait_group 0;" ::: "memory");
}
__device__ __forceinline__ void ldsm_x4(uint32_t& r0, uint32_t& r1, uint32_t& r2, uint32_t& r3,
                                        uint32_t addr) {
    asm volatile("ldmatrix.sync.aligned.m8n8.x4.shared.b16 {%0,%1,%2,%3}, [%4];"
                 : "=r"(r0), "=r"(r1), "=r"(r2), "=r"(r3) : "r"(addr));
}
__device__ __forceinline__ void mma16816(
    float* d, uint32_t a0, uint32_t a1, uint32_t a2, uint32_t a3,
    uint32_t b0, uint32_t b1)
{
    asm volatile(
        "mma.sync.aligned.m16n8k16.row.col.f32.f16.f16.f32 "
        "{%0,%1,%2,%3}, {%4,%5,%6,%7}, {%8,%9}, {%0,%1,%2,%3};"
        : "+f"(d[0]), "+f"(d[1]), "+f"(d[2]), "+f"(d[3])
        : "r"(a0), "r"(a1), "r"(a2), "r"(a3), "r"(b0), "r"(b1));
}

// ---------------- prep: transpose feats -> fp16, compute dim boxes --------
__global__ __launch_bounds__(256) void prep_kernel(
    const float* __restrict__ feats, const float* __restrict__ boxes)
{
    int idx = blockIdx.x * blockDim.x + threadIdx.x;   // over B*N
    if (idx >= BB * NN) return;
    int b = idx >> 17;
    int n = idx & (NN - 1);

    float tmp[CC];
    #pragma unroll
    for (int c = 0; c < CC; c++)
        tmp[c] = feats[(b * CC + c) * NN + n];

    uint32_t u[16];
    #pragma unroll
    for (int p = 0; p < 16; p++) {
        __half2 h = __floats2half2_rn(tmp[2*p], tmp[2*p+1]);
        u[p] = *(uint32_t*)&h;
    }
    uint4* dst = (uint4*)(g_feats_h + ((size_t)idx << 5));
    #pragma unroll
    for (int q = 0; q < 4; q++)
        dst[q] = make_uint4(u[4*q], u[4*q+1], u[4*q+2], u[4*q+3]);

    const float* bx = boxes + (size_t)idx * 6;
    float* dd = g_dimbox + (size_t)idx * 3;
    dd[0] = bx[3] - bx[0];
    dd[1] = bx[4] - bx[1];
    dd[2] = bx[5] - bx[2];
}

// ---------------- fps gather ----------
__global__ __launch_bounds__(256) void fps_kernel(
    const float* __restrict__ locs, const float* __restrict__ boxes,
    const int* __restrict__ fps_inds, float* __restrict__ out)
{
    int idx = blockIdx.x * blockDim.x + threadIdx.x;   // over B*S
    if (idx >= BB * SS) return;
    int b = idx >> 10;
    int j = fps_inds[idx];

    const float* lp = locs + ((size_t)b * NN + j) * 3;
    float l0 = lp[0], l1 = lp[1], l2 = lp[2];
    g_fps_locs[idx*3+0] = l0; g_fps_locs[idx*3+1] = l1; g_fps_locs[idx*3+2] = l2;
    out[OFF_LOCS + idx*3 + 0] = l0;
    out[OFF_LOCS + idx*3 + 1] = l1;
    out[OFF_LOCS + idx*3 + 2] = l2;

    const float* bx = boxes + ((size_t)b * NN + j) * 6;
    float b0 = bx[0], b1 = bx[1], b2 = bx[2], b3 = bx[3], b4 = bx[4], b5 = bx[5];
    g_fps_dim[idx*3+0] = b3 - b0;
    g_fps_dim[idx*3+1] = b4 - b1;
    g_fps_dim[idx*3+2] = b5 - b2;
    out[OFF_BOXES + idx*6 + 0] = b0;
    out[OFF_BOXES + idx*6 + 1] = b1;
    out[OFF_BOXES + idx*6 + 2] = b2;
    out[OFF_BOXES + idx*6 + 3] = b3;
    out[OFF_BOXES + idx*6 + 4] = b4;
    out[OFF_BOXES + idx*6 + 5] = b5;

    out[OFF_INDS + idx] = (float)j;
}

// ================= stage 1: warp-HMMA, 1 warp = 1 query ==================
// K-order: k=0..31 feats, k=32..37 geo, k=38..47 pad (B rows reordered identically)
#define S1H_STRA 56
#define S1H_STR2 40
#define S1H_ATILE (64 * S1H_STRA)                 // 3584 halves
#define S1H_BASE  (32*S1H_STRA + 64*S1H_STR2)     // 4352 halves
#define S1H_SMEM  ((S1H_BASE + 8*S1H_ATILE) * 2)  // 66048 bytes

__global__ __launch_bounds__(256, 3) void stage1_mma_kernel(
    const float* __restrict__ locs, const int* __restrict__ nbr,
    const float* __restrict__ w1a, const float* __restrict__ s1a, const float* __restrict__ t1a,
    const float* __restrict__ w1b, const float* __restrict__ s1b, const float* __restrict__ t1b)
{
    extern __shared__ __half hs1[];
    __half* Bs1 = hs1;                       // [c=32][k<48] stride 56
    __half* Bs2 = hs1 + 32*S1H_STRA;         // [c=64][k<32] stride 40
    __shared__ float ba[CC], bb[HH];
    int tid  = threadIdx.x;
    int warp = tid >> 5;
    int lane = tid & 31;
    __half* A1 = hs1 + S1H_BASE + warp * S1H_ATILE;   // [nbr=64][k<48] stride 56

    int bs = blockIdx.x * 8 + warp;
    int b  = bs >> 10;

    // stage A1: feats via cp.async (k=0..31), geo (k=32..37), pad 38..47
    #pragma unroll
    for (int rr = 0; rr < 2; rr++) {
        int nb = lane + rr * 32;
        int j  = nbr[bs * KK + nb];
        __half* row = A1 + nb * S1H_STRA;
        uint32_t rsm = smem_u32(row);
        const __half* src = g_feats_h + (((size_t)b * NN + j) << 5);
        #pragma unroll
        for (int q = 0; q < 4; q++) cp_async16(rsm + 16*q, src + 8*q);

        const float* lp = locs + ((size_t)b * NN + j) * 3;
        float gx = (lp[0] - g_fps_locs[bs*3+0]) * 2.5f;
        float gy = (lp[1] - g_fps_locs[bs*3+1]) * 2.5f;
        float gz = (lp[2] - g_fps_locs[bs*3+2]) * 2.5f;
        const float* dp = g_dimbox + ((size_t)b * NN + j) * 3;
        float dx = fabsf(dp[0] - g_fps_dim[bs*3+0]);
        float dy = fabsf(dp[1] - g_fps_dim[bs*3+1]);
        float dz = fabsf(dp[2] - g_fps_dim[bs*3+2]);
        *(__half2*)(row + 32) = __floats2half2_rn(gx, gy);
        *(__half2*)(row + 34) = __floats2half2_rn(gz, dx);
        *(__half2*)(row + 36) = __floats2half2_rn(dy, dz);
        #pragma unroll
        for (int k = 38; k < 48; k += 2)
            *(uint32_t*)(row + k) = 0u;
    }

    // stage folded weights (same K-order)
    for (int idx = tid; idx < 32 * 48; idx += 256) {
        int c = idx / 48, k = idx % 48;
        float v;
        if (k < 32)      v = w1a[(6 + k) * CC + c] * s1a[c];
        else if (k < 38) v = w1a[(k - 32) * CC + c] * s1a[c];
        else             v = 0.0f;
        Bs1[c * S1H_STRA + k] = __float2half(v);
    }
    for (int idx = tid; idx < 64 * 32; idx += 256) {
        int c = idx >> 5, k = idx & 31;
        Bs2[c * S1H_STR2 + k] = __float2half(w1b[k * HH + c] * s1b[c]);
    }
    if (tid < CC) ba[tid] = t1a[tid];
    if (tid < HH) bb[tid] = t1b[tid];

    cp_async_wait_all();
    __syncthreads();

    int grp = lane >> 2;   // 0..7
    int tig = lane & 3;    // 0..3
    __half* As2 = A1;      // overlay: writes stay below future reads

    // ldmatrix lane-offset terms (halves -> bytes at use)
    int a_row = lane & 15, a_kh = (lane >> 4) * 8;
    int b_row = ((lane >> 4) & 1) * 8 + (lane & 7), b_kh = ((lane >> 3) & 1) * 8;

    uint32_t A1b  = smem_u32(A1)  + (uint32_t)(a_row * S1H_STRA + a_kh) * 2;
    uint32_t B1b  = smem_u32(Bs1) + (uint32_t)(b_row * S1H_STRA + b_kh) * 2;

    // ---- GEMM1 + fused bias/relu -> As2 fp16 ----
    #pragma unroll
    for (int mt = 0; mt < 4; mt++) {
        float acc[4][4];
        #pragma unroll
        for (int nt = 0; nt < 4; nt++)
            #pragma unroll
            for (int i = 0; i < 4; i++) acc[nt][i] = 0.0f;

        #pragma unroll
        for (int kt = 0; kt < 3; kt++) {
            uint32_t a0, a1, a2, a3;
            ldsm_x4(a0, a1, a2, a3, A1b + (uint32_t)(mt*16*S1H_STRA + kt*16) * 2);
            #pragma unroll
            for (int p = 0; p < 2; p++) {
                uint32_t b0, b1, b2, b3;
                ldsm_x4(b0, b1, b2, b3, B1b + (uint32_t)(p*16*S1H_STRA + kt*16) * 2);
                mma16816(acc[2*p],   a0, a1, a2, a3, b0, b1);
                mma16816(acc[2*p+1], a0, a1, a2, a3, b2, b3);
            }
        }
        __syncwarp();
        #pragma unroll
        for (int nt = 0; nt < 4; nt++) {
            int c0 = nt * 8 + 2 * tig;
            float b0 = ba[c0], b1 = ba[c0 + 1];
            int r0 = mt * 16 + grp;
            __half2 lo = __floats2half2_rn(fmaxf(acc[nt][0] + b0, 0.0f),
                                           fmaxf(acc[nt][1] + b1, 0.0f));
            __half2 hi = __floats2half2_rn(fmaxf(acc[nt][2] + b0, 0.0f),
                                           fmaxf(acc[nt][3] + b1, 0.0f));
            *(__half2*)(As2 + r0 * S1H_STR2 + c0)       = lo;
            *(__half2*)(As2 + (r0 + 8) * S1H_STR2 + c0) = hi;
        }
        __syncwarp();
    }

    // ---- GEMM2 + running max, nt split in halves of 4 ----
    uint32_t A2b = smem_u32(As2) + (uint32_t)(a_row * S1H_STR2 + a_kh) * 2;
    uint32_t B2b = smem_u32(Bs2) + (uint32_t)(b_row * S1H_STR2 + b_kh) * 2;

    float m0[8], m1[8];
    #pragma unroll
    for (int nt = 0; nt < 8; nt++) { m0[nt] = -3.4e38f; m1[nt] = -3.4e38f; }

    #pragma unroll
    for (int mt = 0; mt < 4; mt++) {
        #pragma unroll
        for (int half = 0; half < 2; half++) {
            float acc[4][4];
            #pragma unroll
            for (int q = 0; q < 4; q++)
                #pragma unroll
                for (int i = 0; i < 4; i++) acc[q][i] = 0.0f;

            #pragma unroll
            for (int kt = 0; kt < 2; kt++) {
                uint32_t a0, a1, a2, a3;
                ldsm_x4(a0, a1, a2, a3, A2b + (uint32_t)(mt*16*S1H_STR2 + kt*16) * 2);
                #pragma unroll
                for (int p = 0; p < 2; p++) {
                    uint32_t b0, b1, b2, b3;
                    ldsm_x4(b0, b1, b2, b3,
                            B2b + (uint32_t)((half*2+p)*16*S1H_STR2 + kt*16) * 2);
                    mma16816(acc[2*p],   a0, a1, a2, a3, b0, b1);
                    mma16816(acc[2*p+1], a0, a1, a2, a3, b2, b3);
                }
            }
            #pragma unroll
            for (int q = 0; q < 4; q++) {
                int nt = half * 4 + q;
                m0[nt] = fmaxf(m0[nt], fmaxf(acc[q][0], acc[q][2]));
                m1[nt] = fmaxf(m1[nt], fmaxf(acc[q][1], acc[q][3]));
            }
        }
    }

    #pragma unroll
    for (int nt = 0; nt < 8; nt++) {
        #pragma unroll
        for (int s = 4; s < 32; s <<= 1) {
            m0[nt] = fmaxf(m0[nt], __shfl_xor_sync(0xffffffffu, m0[nt], s));
            m1[nt] = fmaxf(m1[nt], __shfl_xor_sync(0xffffffffu, m1[nt], s));
        }
    }
    if (grp == 0) {
        #pragma unroll
        for (int nt = 0; nt < 8; nt++) {
            int c0 = nt * 8 + 2 * tig;
            float v0 = fmaxf(m0[nt] + bb[c0], 0.0f);
            float v1 = fmaxf(m1[nt] + bb[c0 + 1], 0.0f);
            g_newfeat[bs * HH + c0]     = v0;
            g_newfeat[bs * HH + c0 + 1] = v1;
            *(__half2*)(g_newfeat_h + bs * HH + c0) = __floats2half2_rn(v0, v1);
        }
    }
}

// ================= stage 2: warp-HMMA, cp.async + ldmatrix ===============
// K-order: k=0..63 feats, k=64..69 geo, k=70..79 pad
#define S2H_STRIDE 88
#define S2H_TILE   (64 * S2H_STRIDE)
#define S2H_SMEM   ((S2H_TILE * 9) * 2)              // 101376 bytes

__global__ __launch_bounds__(256, 2) void stage2_mma_kernel(
    const int* __restrict__ nbr2,
    const float* __restrict__ w2, const float* __restrict__ s2, const float* __restrict__ t2)
{
    extern __shared__ __half hsm[];
    __half* Bs = hsm;                         // [n=64][k<80], stride 88
    int tid  = threadIdx.x;
    int warp = tid >> 5;
    int lane = tid & 31;
    __half* As = hsm + S2H_TILE * (1 + warp); // [nbr=64][k<80], stride 88

    int bs = blockIdx.x * 8 + warp;
    int b  = bs >> 10;

    // stage A: feats via cp.async (k=0..63), geo (k=64..69), pad 70..79
    #pragma unroll
    for (int rr = 0; rr < 2; rr++) {
        int nb = lane + rr * 32;
        int j  = nbr2[bs * KK + nb];
        int fj = (b << 10) + j;
        __half* row = As + nb * S2H_STRIDE;
        uint32_t rsm = smem_u32(row);
        const __half* src = g_newfeat_h + ((size_t)fj << 6);
        #pragma unroll
        for (int q = 0; q < 8; q++) cp_async16(rsm + 16*q, src + 8*q);

        float gx = (g_fps_locs[fj*3+0] - g_fps_locs[bs*3+0]) * 1.25f;
        float gy = (g_fps_locs[fj*3+1] - g_fps_locs[bs*3+1]) * 1.25f;
        float gz = (g_fps_locs[fj*3+2] - g_fps_locs[bs*3+2]) * 1.25f;
        float dx = fabsf(g_fps_dim[fj*3+0] - g_fps_dim[bs*3+0]);
        float dy = fabsf(g_fps_dim[fj*3+1] - g_fps_dim[bs*3+1]);
        float dz = fabsf(g_fps_dim[fj*3+2] - g_fps_dim[bs*3+2]);
        *(__half2*)(row + 64) = __floats2half2_rn(gx, gy);
        *(__half2*)(row + 66) = __floats2half2_rn(gz, dx);
        *(__half2*)(row + 68) = __floats2half2_rn(dy, dz);
        #pragma unroll
        for (int k = 70; k < 80; k += 2)
            *(uint32_t*)(row + k) = 0u;
    }

    // stage B (same K-order)
    for (int idx = tid; idx < 64 * 80; idx += 256) {
        int n = idx / 80, k = idx % 80;
        float v;
        if (k < 64)      v = w2[(6 + k) * HH + n] * s2[n];
        else if (k < 70) v = w2[(k - 64) * HH + n] * s2[n];
        else             v = 0.0f;
        Bs[n * S2H_STRIDE + k] = __float2half(v);
    }

    cp_async_wait_all();
    __syncthreads();

    int grp = lane >> 2;
    int tig = lane & 3;

    int a_row = lane & 15, a_kh = (lane >> 4) * 8;
    int b_row = ((lane >> 4) & 1) * 8 + (lane & 7), b_kh = ((lane >> 3) & 1) * 8;
    uint32_t Ab = smem_u32(As) + (uint32_t)(a_row * S2H_STRIDE + a_kh) * 2;
    uint32_t Bb = smem_u32(Bs) + (uint32_t)(b_row * S2H_STRIDE + b_kh) * 2;

    float m0[8], m1[8];
    #pragma unroll
    for (int nt = 0; nt < 8; nt++) { m0[nt] = -3.4e38f; m1[nt] = -3.4e38f; }

    #pragma unroll
    for (int mt = 0; mt < 4; mt++) {
        #pragma unroll
        for (int half = 0; half < 2; half++) {
            float acc[4][4];
            #pragma unroll
            for (int q = 0; q < 4; q++)
                #pragma unroll
                for (int i = 0; i < 4; i++) acc[q][i] = 0.0f;

            #pragma unroll
            for (int kt = 0; kt < 5; kt++) {
                uint32_t a0, a1, a2, a3;
                ldsm_x4(a0, a1, a2, a3, Ab + (uint32_t)(mt*16*S2H_STRIDE + kt*16) * 2);
                #pragma unroll
                for (int p = 0; p < 2; p++) {
                    uint32_t b0, b1, b2, b3;
                    ldsm_x4(b0, b1, b2, b3,
                            Bb + (uint32_t)((half*2+p)*16*S2H_STRIDE + kt*16) * 2);
                    mma16816(acc[2*p],   a0, a1, a2, a3, b0, b1);
                    mma16816(acc[2*p+1], a0, a1, a2, a3, b2, b3);
                }
            }
            #pragma unroll
            for (int q = 0; q < 4; q++) {
                int nt = half * 4 + q;
                m0[nt] = fmaxf(m0[nt], fmaxf(acc[q][0], acc[q][2]));
                m1[nt] = fmaxf(m1[nt], fmaxf(acc[q][1], acc[q][3]));
            }
        }
    }

    #pragma unroll
    for (int nt = 0; nt < 8; nt++) {
        #pragma unroll
        for (int s = 4; s < 32; s <<= 1) {
            m0[nt] = fmaxf(m0[nt], __shfl_xor_sync(0xffffffffu, m0[nt], s));
            m1[nt] = fmaxf(m1[nt], __shfl_xor_sync(0xffffffffu, m1[nt], s));
        }
    }
    if (grp == 0) {
        #pragma unroll
        for (int nt = 0; nt < 8; nt++) {
            int c0 = nt * 8 + 2 * tig;
            g_h2max[bs * HH + c0]     = m0[nt] + t2[c0];
            g_h2max[bs * HH + c0 + 1] = m1[nt] + t2[c0 + 1];
        }
    }
}

// ---------------- stage 3: bottleneck mlp3 + skip, write transposed ------
#define TS 16
__global__ __launch_bounds__(256) void stage3_kernel(
    const float* __restrict__ w3a, const float* __restrict__ s3a, const float* __restrict__ t3a,
    const float* __restrict__ w3b, const float* __restrict__ s3b, const float* __restrict__ t3b,
    float* __restrict__ out)
{
    __shared__ float h2s[TS * HH];
    __shared__ float h3s[TS * H3];
    int t = threadIdx.x;
    int row0 = blockIdx.x * TS;

    for (int i = t; i < TS * HH; i += 256) h2s[i] = g_h2max[row0 * HH + i];
    __syncthreads();

    {
        float sc = s3a[t], bi = t3a[t];
        float acc[TS];
        #pragma unroll
        for (int r = 0; r < TS; r++) acc[r] = bi;
        #pragma unroll 4
        for (int i = 0; i < HH; i++) {
            float wv = w3a[i * H3 + t] * sc;
            #pragma unroll
            for (int r = 0; r < TS; r++) acc[r] += h2s[r * HH + i] * wv;
        }
        #pragma unroll
        for (int r = 0; r < TS; r++) h3s[r * H3 + t] = fmaxf(acc[r], 0.0f);
    }
    __syncthreads();

    {
        int c  = t & 63;
        int rg = t >> 6;
        float sc = s3b[c], bi = t3b[c];
        float acc[4];
        #pragma unroll
        for (int rr = 0; rr < 4; rr++) acc[rr] = bi;
        #pragma unroll 4
        for (int i = 0; i < H3; i++) {
            float wv = w3b[i * HH + c] * sc;
            #pragma unroll
            for (int rr = 0; rr < 4; rr++)
                acc[rr] += h3s[(rg * 4 + rr) * H3 + i] * wv;
        }
        #pragma unroll
        for (int rr = 0; rr < 4; rr++) {
            int row = row0 + rg * 4 + rr;
            int b = row >> 10, s = row & 1023;
            float v = acc[rr] + g_newfeat[row * HH + c];
            out[OFF_OUT + ((b * HH + c) << 10) + s] = fmaxf(v, 0.0f);
        }
    }
}

// ---------------- launch ----------------
extern "C" void kernel_launch(void* const* d_in, const int* in_sizes, int n_in,
                              void* d_out, int out_size)
{
    const float* locs  = (const float*)d_in[0];
    const float* feats = (const float*)d_in[1];
    const float* boxes = (const float*)d_in[2];
    const int*   fps   = (const int*)d_in[3];
    const int*   nbr   = (const int*)d_in[4];
    const int*   nbr2  = (const int*)d_in[5];
    const float* w1a = (const float*)d_in[6];
    const float* s1a = (const float*)d_in[7];
    const float* t1a = (const float*)d_in[8];
    const float* w1b = (const float*)d_in[9];
    const float* s1b = (const float*)d_in[10];
    const float* t1b = (const float*)d_in[11];
    const float* w2  = (const float*)d_in[12];
    const float* s2  = (const float*)d_in[13];
    const float* t2  = (const float*)d_in[14];
    const float* w3a = (const float*)d_in[15];
    const float* s3a = (const float*)d_in[16];
    const float* t3a = (const float*)d_in[17];
    const float* w3b = (const float*)d_in[18];
    const float* s3b = (const float*)d_in[19];
    const float* t3b = (const float*)d_in[20];
    float* out = (float*)d_out;

    cudaFuncSetAttribute(stage1_mma_kernel, cudaFuncAttributeMaxDynamicSharedMemorySize, S1H_SMEM);
    cudaFuncSetAttribute(stage2_mma_kernel, cudaFuncAttributeMaxDynamicSharedMemorySize, S2H_SMEM);

    prep_kernel<<<(BB * NN + 255) / 256, 256>>>(feats, boxes);
    fps_kernel<<<(BB * SS + 255) / 256, 256>>>(locs, boxes, fps, out);
    stage1_mma_kernel<<<BB * SS / 8, 256, S1H_SMEM>>>(locs, nbr, w1a, s1a, t1a, w1b, s1b, t1b);
    stage2_mma_kernel<<<BB * SS / 8, 256, S2H_SMEM>>>(nbr2, w2, s2, t2);
    stage3_kernel<<<(BB * SS) / TS, 256>>>(w3a, s3a, t3a, w3b, s3b, t3b, out);
}